// round 1
// baseline (speedup 1.0000x reference)
#include <cuda_runtime.h>
#include <math.h>

namespace {

constexpr int B_ = 32;
constexpr int N_ = 64;
constexpr int C_ = 128;
constexpr int M_ = 15;
constexpr int E_ = B_ * N_ * N_;   // 131072
constexpr float LN_EPS = 1e-5f;

// ---------------- device scratch (allocation-free: __device__ globals) ------
__device__ __align__(16) float g_t[(size_t)E_ * C_];      // 64 MB: post-LN activations
__device__ __align__(16) float g_row [B_ * N_ * C_];
__device__ __align__(16) float g_col [B_ * N_ * C_];
__device__ __align__(16) float g_diag[B_ * N_ * C_];
__device__ __align__(16) float g_trace[B_ * C_];
__device__ __align__(16) float g_tot  [B_ * C_];
__device__ __align__(16) float g_A [B_ * N_ * C_];
__device__ __align__(16) float g_Bv[B_ * N_ * C_];
__device__ __align__(16) float g_D [B_ * N_ * C_];
__device__ __align__(16) float g_Cc[B_ * C_];
__device__ __align__(16) float g_Ec[B_ * C_];
// transposed per-map weights: g_WT[m][c][o] = coeffs[o,c,m]
__device__ __align__(16) float g_WT[M_ * C_ * C_];

__device__ __forceinline__ float gelu_exact(float v) {
    return 0.5f * v * (1.0f + erff(v * 0.70710678118654752440f));
}

// ---------------- K0: build transposed coefficient matrices -----------------
// coeffs[o,c,m] = c00[o,m]*c10[o,c] + c01[c,m]*c11[o,c]; stored as WT[m][c][o]
__global__ void k_coeffs(const float* __restrict__ c00, const float* __restrict__ c01,
                         const float* __restrict__ c10, const float* __restrict__ c11) {
    int idx = blockIdx.x * blockDim.x + threadIdx.x;
    if (idx >= M_ * C_ * C_) return;
    int o = idx & (C_ - 1);
    int c = (idx >> 7) & (C_ - 1);
    int m = idx >> 14;
    g_WT[idx] = c00[o * M_ + m] * c10[o * C_ + c] + c01[c * M_ + m] * c11[o * C_ + c];
}

// ---------------- K1: h = LN(GELU(x @ W_in^T + b)) -> g_t; fused row-mean ---
// One block = one (b,i) slab of 64 rows x 128 cols. 256 threads.
__global__ void k_input(const float* __restrict__ x, const float* __restrict__ Wi,
                        const float* __restrict__ bi, const float* __restrict__ lg,
                        const float* __restrict__ lb) {
    extern __shared__ float sm[];
    float* Ws = sm;                       // [128][132]  transposed W_in (padded)
    float* Xs = sm + 128 * 132;           // [64][128]   x tile, reused for h
    float* rowsum = Xs + N_ * C_;         // [128]
    const int tid = threadIdx.x;
    const int p = blockIdx.x;             // (b*64 + i)
    const size_t base = (size_t)p * (N_ * C_);

    if (tid < C_) rowsum[tid] = 0.f;
    // transpose W_in into smem: Ws[c][o] = Wi[o*128+c]
    for (int idx = tid; idx < C_ * C_; idx += 256) {
        int o = idx >> 7, c = idx & 127;
        Ws[c * 132 + o] = Wi[idx];
    }
    {   // x tile is 64 contiguous rows
        const float4* src = reinterpret_cast<const float4*>(x + base);
        float4* dst = reinterpret_cast<float4*>(Xs);
        for (int idx = tid; idx < N_ * C_ / 4; idx += 256) dst[idx] = src[idx];
    }
    __syncthreads();

    const int warp = tid >> 5, lane = tid & 31;
    const int r0 = warp * 8;      // warp privately owns 8 rows
    const int o0 = lane * 4;      // 4 output cols per lane
    float acc[8][4];
#pragma unroll
    for (int r = 0; r < 8; r++) { acc[r][0] = acc[r][1] = acc[r][2] = acc[r][3] = 0.f; }

#pragma unroll 4
    for (int k = 0; k < C_; k++) {
        float4 w = *reinterpret_cast<const float4*>(&Ws[k * 132 + o0]);
#pragma unroll
        for (int r = 0; r < 8; r++) {
            float xv = Xs[(r0 + r) * C_ + k];   // warp-uniform broadcast
            acc[r][0] = fmaf(xv, w.x, acc[r][0]);
            acc[r][1] = fmaf(xv, w.y, acc[r][1]);
            acc[r][2] = fmaf(xv, w.z, acc[r][2]);
            acc[r][3] = fmaf(xv, w.w, acc[r][3]);
        }
    }
    __syncwarp();   // warp's rows are private: warp-level barrier suffices
    const float4 bia = *reinterpret_cast<const float4*>(bi + o0);
#pragma unroll
    for (int r = 0; r < 8; r++) {
        float4 g;
        g.x = gelu_exact(acc[r][0] + bia.x);
        g.y = gelu_exact(acc[r][1] + bia.y);
        g.z = gelu_exact(acc[r][2] + bia.z);
        g.w = gelu_exact(acc[r][3] + bia.w);
        *reinterpret_cast<float4*>(&Xs[(r0 + r) * C_ + o0]) = g;
    }
    __syncwarp();

    const float lg0 = lg[lane], lg1 = lg[lane + 32], lg2 = lg[lane + 64], lg3 = lg[lane + 96];
    const float lb0 = lb[lane], lb1 = lb[lane + 32], lb2 = lb[lane + 64], lb3 = lb[lane + 96];
#pragma unroll
    for (int r = 0; r < 8; r++) {
        const float* hr = &Xs[(r0 + r) * C_];
        float v0 = hr[lane], v1 = hr[lane + 32], v2 = hr[lane + 64], v3 = hr[lane + 96];
        float s  = v0 + v1 + v2 + v3;
        float ss = v0 * v0 + v1 * v1 + v2 * v2 + v3 * v3;
#pragma unroll
        for (int off = 16; off; off >>= 1) {
            s  += __shfl_xor_sync(0xffffffffu, s,  off);
            ss += __shfl_xor_sync(0xffffffffu, ss, off);
        }
        float mu  = s * (1.0f / C_);
        float var = ss * (1.0f / C_) - mu * mu;
        float inv = rsqrtf(var + LN_EPS);
        float n0 = (v0 - mu) * inv * lg0 + lb0;
        float n1 = (v1 - mu) * inv * lg1 + lb1;
        float n2 = (v2 - mu) * inv * lg2 + lb2;
        float n3 = (v3 - mu) * inv * lg3 + lb3;
        size_t ob = base + (size_t)(r0 + r) * C_;
        g_t[ob + lane] = n0; g_t[ob + lane + 32] = n1;
        g_t[ob + lane + 64] = n2; g_t[ob + lane + 96] = n3;
        atomicAdd(&rowsum[lane],      n0);
        atomicAdd(&rowsum[lane + 32], n1);
        atomicAdd(&rowsum[lane + 64], n2);
        atomicAdd(&rowsum[lane + 96], n3);
    }
    __syncthreads();
    if (tid < C_) g_row[p * C_ + tid] = rowsum[tid] * (1.0f / N_);
}

// ---------------- K2: col means + diag --------------------------------------
__global__ void k_coldiag() {
    int p = blockIdx.x, c = threadIdx.x;       // p = (b*64 + q)
    int b = p >> 6, q = p & 63;
    float s = 0.f;
    const size_t stride = (size_t)N_ * C_;
    size_t baseq = (size_t)(b * N_ * N_) * C_ + (size_t)q * C_ + c;
    for (int i2 = 0; i2 < N_; i2++) s += g_t[baseq + (size_t)i2 * stride];
    g_col[p * C_ + c] = s * (1.0f / N_);
    g_diag[p * C_ + c] = g_t[((size_t)((b * N_ + q) * N_ + q)) * C_ + c];
}

// ---------------- K2b: trace / tot ------------------------------------------
__global__ void k_tracetot() {
    int b = blockIdx.x, c = threadIdx.x;
    float st = 0.f, so = 0.f;
    for (int q = 0; q < N_; q++) {
        st += g_diag[(b * N_ + q) * C_ + c];
        so += g_row [(b * N_ + q) * C_ + c];
    }
    g_trace[b * C_ + c] = st * (1.0f / N_);
    g_tot  [b * C_ + c] = so * (1.0f / N_);
}

// ---------------- K3a: A, Bv, D (maps 2..7, 10..12) -------------------------
// block: 32 (b,i)-rows, 512 threads (4 row-groups x 128 output cols)
__global__ void k_abd() {
    extern __shared__ float sm[];
    float* sd = sm;                 // [32][128] diag
    float* sr = sd + 32 * C_;       // row
    float* sc = sr + 32 * C_;       // col
    const int tid = threadIdx.x;
    const int rb = blockIdx.x * 32;
    for (int idx = tid; idx < 32 * C_; idx += 512) {
        sd[idx] = g_diag[rb * C_ + idx];
        sr[idx] = g_row [rb * C_ + idx];
        sc[idx] = g_col [rb * C_ + idx];
    }
    __syncthreads();
    const int o = tid & 127, grp = tid >> 7;
    const float* W2  = g_WT + 2  * C_ * C_;
    const float* W3  = g_WT + 3  * C_ * C_;
    const float* W4  = g_WT + 4  * C_ * C_;
    const float* W5  = g_WT + 5  * C_ * C_;
    const float* W6  = g_WT + 6  * C_ * C_;
    const float* W7  = g_WT + 7  * C_ * C_;
    const float* W10 = g_WT + 10 * C_ * C_;
    const float* W11 = g_WT + 11 * C_ * C_;
    const float* W12 = g_WT + 12 * C_ * C_;
    float aA[8], aB[8], aD[8];
#pragma unroll
    for (int r = 0; r < 8; r++) { aA[r] = aB[r] = aD[r] = 0.f; }
    for (int c = 0; c < C_; c++) {
        int wi = c * C_ + o;
        float w2 = W2[wi], w3 = W3[wi], w4 = W4[wi], w5 = W5[wi];
        float w6 = W6[wi], w7 = W7[wi], wa = W10[wi], wb = W11[wi], wc = W12[wi];
#pragma unroll
        for (int r = 0; r < 8; r++) {
            int rr = grp * 8 + r;
            float d = sd[rr * C_ + c], ro = sr[rr * C_ + c], co = sc[rr * C_ + c];
            aA[r] = fmaf(w2, d, fmaf(w4, ro, fmaf(w6, co, aA[r])));
            aB[r] = fmaf(w3, d, fmaf(w5, ro, fmaf(w7, co, aB[r])));
            aD[r] = fmaf(wa, d, fmaf(wb, ro, fmaf(wc, co, aD[r])));
        }
    }
#pragma unroll
    for (int r = 0; r < 8; r++) {
        int rr = rb + grp * 8 + r;
        g_A [rr * C_ + o] = aA[r];
        g_Bv[rr * C_ + o] = aB[r];
        g_D [rr * C_ + o] = aD[r];
    }
}

// ---------------- K3b: Cc, Ec (maps 8,9,13,14) ------------------------------
__global__ void k_ce() {
    __shared__ float str[C_], sto[C_];
    int b = blockIdx.x, o = threadIdx.x;
    str[o] = g_trace[b * C_ + o];
    sto[o] = g_tot  [b * C_ + o];
    __syncthreads();
    const float* W8  = g_WT + 8  * C_ * C_;
    const float* W9  = g_WT + 9  * C_ * C_;
    const float* W13 = g_WT + 13 * C_ * C_;
    const float* W14 = g_WT + 14 * C_ * C_;
    float a = 0.f, e = 0.f;
    for (int c = 0; c < C_; c++) {
        int wi = c * C_ + o;
        float tr = str[c], to = sto[c];
        a = fmaf(W8 [wi], tr, fmaf(W9 [wi], to, a));
        e = fmaf(W13[wi], tr, fmaf(W14[wi], to, e));
    }
    g_Cc[b * C_ + o] = a;
    g_Ec[b * C_ + o] = e;
}

// ---------------- K4: main — out = GELU(W0 t + W1 t^T + broadcasts) ---------
// block = one (b,i): 64 rows (all j). 256 threads, 192 KB smem.
__global__ void k_main(float* __restrict__ out) {
    extern __shared__ float sm[];
    float* Ws0 = sm;                   // [128][128] WT map 0
    float* Ws1 = Ws0 + C_ * C_;        // [128][128] WT map 1
    float* T1  = Ws1 + C_ * C_;        // [64][128] t[b,i,j,:]
    float* T2  = T1 + N_ * C_;         // [64][128] t[b,j,i,:]
    const int tid = threadIdx.x;
    const int p = blockIdx.x;
    const int b = p >> 6, i = p & 63;
    const size_t base = (size_t)p * (N_ * C_);

    {
        const float4* s0 = reinterpret_cast<const float4*>(g_WT);
        const float4* s1 = reinterpret_cast<const float4*>(g_WT + C_ * C_);
        float4* d0 = reinterpret_cast<float4*>(Ws0);
        float4* d1 = reinterpret_cast<float4*>(Ws1);
        for (int idx = tid; idx < C_ * C_ / 4; idx += 256) { d0[idx] = s0[idx]; d1[idx] = s1[idx]; }
    }
    {
        const float4* src = reinterpret_cast<const float4*>(g_t + base);
        float4* dst = reinterpret_cast<float4*>(T1);
        for (int idx = tid; idx < N_ * C_ / 4; idx += 256) dst[idx] = src[idx];
    }
    {
        float4* dst = reinterpret_cast<float4*>(T2);
        for (int idx = tid; idx < N_ * C_ / 4; idx += 256) {
            int j = idx >> 5, q = idx & 31;
            const float4* src =
                reinterpret_cast<const float4*>(g_t + ((size_t)((b * N_ + j) * N_ + i)) * C_);
            dst[idx] = src[q];
        }
    }
    __syncthreads();

    const int warp = tid >> 5, lane = tid & 31;
    const int j0 = warp * 8, o0 = lane * 4;
    float acc[8][4];
#pragma unroll
    for (int r = 0; r < 8; r++) { acc[r][0] = acc[r][1] = acc[r][2] = acc[r][3] = 0.f; }

#pragma unroll 2
    for (int k = 0; k < C_; k++) {
        float4 w0 = *reinterpret_cast<const float4*>(&Ws0[k * C_ + o0]);
        float4 w1 = *reinterpret_cast<const float4*>(&Ws1[k * C_ + o0]);
#pragma unroll
        for (int r = 0; r < 8; r++) {
            float a  = T1[(j0 + r) * C_ + k];
            float bb = T2[(j0 + r) * C_ + k];
            acc[r][0] = fmaf(a, w0.x, fmaf(bb, w1.x, acc[r][0]));
            acc[r][1] = fmaf(a, w0.y, fmaf(bb, w1.y, acc[r][1]));
            acc[r][2] = fmaf(a, w0.z, fmaf(bb, w1.z, acc[r][2]));
            acc[r][3] = fmaf(a, w0.w, fmaf(bb, w1.w, acc[r][3]));
        }
    }

    const float4 av = *reinterpret_cast<const float4*>(g_A  + (size_t)p * C_ + o0);
    const float4 cv = *reinterpret_cast<const float4*>(g_Cc + (size_t)b * C_ + o0);
    const float4 dv = *reinterpret_cast<const float4*>(g_D  + (size_t)p * C_ + o0);
    const float4 ev = *reinterpret_cast<const float4*>(g_Ec + (size_t)b * C_ + o0);
    const float add0 = av.x + cv.x, add1 = av.y + cv.y, add2 = av.z + cv.z, add3 = av.w + cv.w;
    const float dia0 = dv.x + ev.x, dia1 = dv.y + ev.y, dia2 = dv.z + ev.z, dia3 = dv.w + ev.w;
#pragma unroll
    for (int r = 0; r < 8; r++) {
        int j = j0 + r;
        float4 bv = *reinterpret_cast<const float4*>(g_Bv + ((size_t)(b * N_ + j)) * C_ + o0);
        float e0 = acc[r][0] + add0 + bv.x;
        float e1 = acc[r][1] + add1 + bv.y;
        float e2 = acc[r][2] + add2 + bv.z;
        float e3 = acc[r][3] + add3 + bv.w;
        if (j == i) { e0 += dia0; e1 += dia1; e2 += dia2; e3 += dia3; }
        float4 o4;
        o4.x = gelu_exact(e0); o4.y = gelu_exact(e1);
        o4.z = gelu_exact(e2); o4.w = gelu_exact(e3);
        *reinterpret_cast<float4*>(out + base + (size_t)j * C_ + o0) = o4;
    }
}

} // anonymous namespace

// ---------------- launch -----------------------------------------------------
extern "C" void kernel_launch(void* const* d_in, const int* in_sizes, int n_in,
                              void* d_out, int out_size) {
    const float* x   = (const float*)d_in[0];
    // d_in[1] = edge_index, d_in[2] = batch: structurally fixed, unused
    const float* Wi  = (const float*)d_in[3];
    const float* bi  = (const float*)d_in[4];
    const float* lg  = (const float*)d_in[5];
    const float* lb  = (const float*)d_in[6];
    const float* c00 = (const float*)d_in[7];
    const float* c01 = (const float*)d_in[8];
    const float* c10 = (const float*)d_in[9];
    const float* c11 = (const float*)d_in[10];
    float* out = (float*)d_out;

    const size_t smem_in   = (size_t)(128 * 132 + 64 * 128 + 128) * sizeof(float); // ~98.5 KB
    const size_t smem_abd  = (size_t)(3 * 32 * 128) * sizeof(float);               // 48 KB
    const size_t smem_main = (size_t)(2 * 128 * 128 + 2 * 64 * 128) * sizeof(float); // 192 KB
    cudaFuncSetAttribute(k_input, cudaFuncAttributeMaxDynamicSharedMemorySize, (int)smem_in);
    cudaFuncSetAttribute(k_abd,   cudaFuncAttributeMaxDynamicSharedMemorySize, (int)smem_abd);
    cudaFuncSetAttribute(k_main,  cudaFuncAttributeMaxDynamicSharedMemorySize, (int)smem_main);

    k_coeffs<<<(M_ * C_ * C_ + 255) / 256, 256>>>(c00, c01, c10, c11);
    k_input<<<B_ * N_, 256, smem_in>>>(x, Wi, bi, lg, lb);
    k_coldiag<<<B_ * N_, 128>>>();
    k_tracetot<<<B_, 128>>>();
    k_abd<<<64, 512, smem_abd>>>();
    k_ce<<<B_, 128>>>();
    k_main<<<B_ * N_, 256, smem_main>>>(out);
}

// round 2
// speedup vs baseline: 1.0069x; 1.0069x over previous
#include <cuda_runtime.h>
#include <math.h>

namespace {

constexpr int B_ = 32;
constexpr int N_ = 64;
constexpr int C_ = 128;
constexpr int M_ = 15;
constexpr int E_ = B_ * N_ * N_;   // 131072
constexpr float LN_EPS = 1e-5f;
constexpr int WSTRIDE = 132;       // padded [o][k] stride (mult of 4 for LDS.128)

// ---------------- device scratch (allocation-free: __device__ globals) ------
__device__ __align__(16) float g_t[(size_t)E_ * C_];      // 64 MB post-LN activations
__device__ __align__(16) float g_row [B_ * N_ * C_];
__device__ __align__(16) float g_col [B_ * N_ * C_];
__device__ __align__(16) float g_diag[B_ * N_ * C_];
__device__ __align__(16) float g_A [B_ * N_ * C_];
__device__ __align__(16) float g_Bv[B_ * N_ * C_];
__device__ __align__(16) float g_D [B_ * N_ * C_];
__device__ __align__(16) float g_Cc[B_ * C_];
__device__ __align__(16) float g_Ec[B_ * C_];
// transposed per-map weights for small projections: g_WT[m][c][o] = coeffs[o,c,m]
__device__ __align__(16) float g_WT[M_ * C_ * C_];
// maps 0,1 pre-padded in [o][k]-with-stride-132 layout (copy linearly into smem)
__device__ __align__(16) float g_Wpad[2 * C_ * WSTRIDE];

union F2U { unsigned long long u; float2 f; };

__device__ __forceinline__ unsigned long long ffma2(unsigned long long a,
                                                    unsigned long long b,
                                                    unsigned long long c) {
    unsigned long long d;
    asm("fma.rn.f32x2 %0, %1, %2, %3;" : "=l"(d) : "l"(a), "l"(b), "l"(c));
    return d;
}
__device__ __forceinline__ float unpack_sum(unsigned long long u) {
    F2U x; x.u = u; return x.f.x + x.f.y;
}

__device__ __forceinline__ float gelu_exact(float v) {
    return 0.5f * v * (1.0f + erff(v * 0.70710678118654752440f));
}

// ---------------- K0: coefficient matrices ----------------------------------
__global__ void k_coeffs(const float* __restrict__ c00, const float* __restrict__ c01,
                         const float* __restrict__ c10, const float* __restrict__ c11) {
    int idx = blockIdx.x * blockDim.x + threadIdx.x;
    if (idx >= M_ * C_ * C_) return;
    int o = idx & (C_ - 1);
    int c = (idx >> 7) & (C_ - 1);
    int m = idx >> 14;
    float v = c00[o * M_ + m] * c10[o * C_ + c] + c01[c * M_ + m] * c11[o * C_ + c];
    g_WT[idx] = v;                                   // [m][c][o]
    if (m < 2) g_Wpad[m * C_ * WSTRIDE + o * WSTRIDE + c] = v;   // [m][o][k] padded
}

// ---------------- K1: g_t = LN(GELU(x @ W_in^T + b)); fused row-mean --------
// block = one (b,i) slab: 64 rows x 128 cols. 256 threads; warp owns 8 rows;
// lane owns outputs {lane, lane+32, lane+64, lane+96}.
__global__ void __launch_bounds__(256) k_input(
        const float* __restrict__ x, const float* __restrict__ Wi,
        const float* __restrict__ bi, const float* __restrict__ lg,
        const float* __restrict__ lb) {
    extern __shared__ float sm[];
    float* Ws = sm;                        // [128][132] W_in as [o][k], padded
    float* Xs = sm + C_ * WSTRIDE;         // [64][128] x tile
    float* rowsum = Xs + N_ * C_;          // [128]
    const int tid = threadIdx.x;
    const int p = blockIdx.x;
    const size_t base = (size_t)p * (N_ * C_);

    if (tid < C_) rowsum[tid] = 0.f;
    // Wi is already [o][k]: copy rows with padding
    for (int idx = tid; idx < C_ * (C_ / 4); idx += 256) {
        int o = idx >> 5, cq = idx & 31;
        *reinterpret_cast<float4*>(&Ws[o * WSTRIDE + cq * 4]) =
            *reinterpret_cast<const float4*>(&Wi[o * C_ + cq * 4]);
    }
    {
        const float4* src = reinterpret_cast<const float4*>(x + base);
        float4* dst = reinterpret_cast<float4*>(Xs);
        for (int idx = tid; idx < N_ * C_ / 4; idx += 256) dst[idx] = src[idx];
    }
    __syncthreads();

    const int warp = tid >> 5, lane = tid & 31;
    const int r0 = warp * 8;
    unsigned long long acc[8][4];
#pragma unroll
    for (int r = 0; r < 8; r++)
#pragma unroll
        for (int q = 0; q < 4; q++) acc[r][q] = 0ull;

    for (int k = 0; k < C_; k += 4) {
        ulonglong2 w[4];
#pragma unroll
        for (int q = 0; q < 4; q++)
            w[q] = *reinterpret_cast<const ulonglong2*>(&Ws[(lane + 32 * q) * WSTRIDE + k]);
#pragma unroll
        for (int r = 0; r < 8; r++) {
            ulonglong2 t = *reinterpret_cast<const ulonglong2*>(&Xs[(r0 + r) * C_ + k]);
#pragma unroll
            for (int q = 0; q < 4; q++) {
                acc[r][q] = ffma2(t.x, w[q].x, acc[r][q]);
                acc[r][q] = ffma2(t.y, w[q].y, acc[r][q]);
            }
        }
    }

    const float b0 = bi[lane], b1 = bi[lane + 32], b2 = bi[lane + 64], b3 = bi[lane + 96];
    const float lg0 = lg[lane], lg1 = lg[lane + 32], lg2 = lg[lane + 64], lg3 = lg[lane + 96];
    const float lb0 = lb[lane], lb1 = lb[lane + 32], lb2 = lb[lane + 64], lb3 = lb[lane + 96];
#pragma unroll
    for (int r = 0; r < 8; r++) {
        float v0 = gelu_exact(unpack_sum(acc[r][0]) + b0);
        float v1 = gelu_exact(unpack_sum(acc[r][1]) + b1);
        float v2 = gelu_exact(unpack_sum(acc[r][2]) + b2);
        float v3 = gelu_exact(unpack_sum(acc[r][3]) + b3);
        float s  = v0 + v1 + v2 + v3;
        float ss = v0 * v0 + v1 * v1 + v2 * v2 + v3 * v3;
#pragma unroll
        for (int off = 16; off; off >>= 1) {
            s  += __shfl_xor_sync(0xffffffffu, s,  off);
            ss += __shfl_xor_sync(0xffffffffu, ss, off);
        }
        float mu  = s * (1.0f / C_);
        float var = ss * (1.0f / C_) - mu * mu;
        float inv = rsqrtf(var + LN_EPS);
        float n0 = (v0 - mu) * inv * lg0 + lb0;
        float n1 = (v1 - mu) * inv * lg1 + lb1;
        float n2 = (v2 - mu) * inv * lg2 + lb2;
        float n3 = (v3 - mu) * inv * lg3 + lb3;
        size_t ob = base + (size_t)(r0 + r) * C_;
        g_t[ob + lane] = n0; g_t[ob + lane + 32] = n1;
        g_t[ob + lane + 64] = n2; g_t[ob + lane + 96] = n3;
        atomicAdd(&rowsum[lane],      n0);
        atomicAdd(&rowsum[lane + 32], n1);
        atomicAdd(&rowsum[lane + 64], n2);
        atomicAdd(&rowsum[lane + 96], n3);
    }
    __syncthreads();
    if (tid < C_) g_row[p * C_ + tid] = rowsum[tid] * (1.0f / N_);
}

// ---------------- K2: col means + diag --------------------------------------
__global__ void k_coldiag() {
    int p = blockIdx.x, c = threadIdx.x;       // p = (b*64 + q)
    int b = p >> 6, q = p & 63;
    float s = 0.f;
    const size_t stride = (size_t)N_ * C_;
    size_t baseq = (size_t)(b * N_ * N_) * C_ + (size_t)q * C_ + c;
    for (int i2 = 0; i2 < N_; i2++) s += g_t[baseq + (size_t)i2 * stride];
    g_col[p * C_ + c] = s * (1.0f / N_);
    g_diag[p * C_ + c] = g_t[((size_t)((b * N_ + q) * N_ + q)) * C_ + c];
}

// ---------------- K3a: A, Bv, D (maps 2..7, 10..12) -------------------------
__global__ void k_abd() {
    extern __shared__ float sm[];
    float* sd = sm;
    float* sr = sd + 32 * C_;
    float* sc = sr + 32 * C_;
    const int tid = threadIdx.x;
    const int rb = blockIdx.x * 32;
    for (int idx = tid; idx < 32 * C_; idx += 512) {
        sd[idx] = g_diag[rb * C_ + idx];
        sr[idx] = g_row [rb * C_ + idx];
        sc[idx] = g_col [rb * C_ + idx];
    }
    __syncthreads();
    const int o = tid & 127, grp = tid >> 7;
    const float* W2  = g_WT + 2  * C_ * C_;
    const float* W3  = g_WT + 3  * C_ * C_;
    const float* W4  = g_WT + 4  * C_ * C_;
    const float* W5  = g_WT + 5  * C_ * C_;
    const float* W6  = g_WT + 6  * C_ * C_;
    const float* W7  = g_WT + 7  * C_ * C_;
    const float* W10 = g_WT + 10 * C_ * C_;
    const float* W11 = g_WT + 11 * C_ * C_;
    const float* W12 = g_WT + 12 * C_ * C_;
    float aA[8], aB[8], aD[8];
#pragma unroll
    for (int r = 0; r < 8; r++) { aA[r] = aB[r] = aD[r] = 0.f; }
    for (int c = 0; c < C_; c++) {
        int wi = c * C_ + o;
        float w2 = W2[wi], w3 = W3[wi], w4 = W4[wi], w5 = W5[wi];
        float w6 = W6[wi], w7 = W7[wi], wa = W10[wi], wb = W11[wi], wc = W12[wi];
#pragma unroll
        for (int r = 0; r < 8; r++) {
            int rr = grp * 8 + r;
            float d = sd[rr * C_ + c], ro = sr[rr * C_ + c], co = sc[rr * C_ + c];
            aA[r] = fmaf(w2, d, fmaf(w4, ro, fmaf(w6, co, aA[r])));
            aB[r] = fmaf(w3, d, fmaf(w5, ro, fmaf(w7, co, aB[r])));
            aD[r] = fmaf(wa, d, fmaf(wb, ro, fmaf(wc, co, aD[r])));
        }
    }
#pragma unroll
    for (int r = 0; r < 8; r++) {
        int rr = rb + grp * 8 + r;
        g_A [rr * C_ + o] = aA[r];
        g_Bv[rr * C_ + o] = aB[r];
        g_D [rr * C_ + o] = aD[r];
    }
}

// ---------------- K3b: trace/tot + Cc, Ec (maps 8,9,13,14) — fused ----------
__global__ void k_ce() {
    __shared__ float str[C_], sto[C_];
    int b = blockIdx.x, o = threadIdx.x;   // thread doubles as c-index for sums
    float st = 0.f, so = 0.f;
    for (int q = 0; q < N_; q++) {
        st += g_diag[(b * N_ + q) * C_ + o];
        so += g_row [(b * N_ + q) * C_ + o];
    }
    str[o] = st * (1.0f / N_);
    sto[o] = so * (1.0f / N_);
    __syncthreads();
    const float* W8  = g_WT + 8  * C_ * C_;
    const float* W9  = g_WT + 9  * C_ * C_;
    const float* W13 = g_WT + 13 * C_ * C_;
    const float* W14 = g_WT + 14 * C_ * C_;
    float a = 0.f, e = 0.f;
    for (int c = 0; c < C_; c++) {
        int wi = c * C_ + o;
        float tr = str[c], to = sto[c];
        a = fmaf(W8 [wi], tr, fmaf(W9 [wi], to, a));
        e = fmaf(W13[wi], tr, fmaf(W14[wi], to, e));
    }
    g_Cc[b * C_ + o] = a;
    g_Ec[b * C_ + o] = e;
}

// ---------------- K4: main — out = GELU(W0 t + W1 t^T + broadcasts) ---------
// block = one (b,i): 64 rows. 256 threads, ~196 KB smem. FFMA2 mainloop.
__global__ void __launch_bounds__(256) k_main(float* __restrict__ out) {
    extern __shared__ float sm[];
    float* Ws0 = sm;                         // [128][132] map-0 weights [o][k]
    float* Ws1 = Ws0 + C_ * WSTRIDE;         // [128][132] map-1 weights
    float* T1  = Ws1 + C_ * WSTRIDE;         // [64][128] t[b,i,j,:]
    float* T2  = T1 + N_ * C_;               // [64][128] t[b,j,i,:]
    const int tid = threadIdx.x;
    const int p = blockIdx.x;
    const int b = p >> 6, i = p & 63;
    const size_t base = (size_t)p * (N_ * C_);

    {   // linear copy of both padded weight maps (layout preserved)
        const float4* src = reinterpret_cast<const float4*>(g_Wpad);
        float4* dst = reinterpret_cast<float4*>(Ws0);     // Ws1 is contiguous after Ws0
        for (int idx = tid; idx < 2 * C_ * WSTRIDE / 4; idx += 256) dst[idx] = src[idx];
    }
    {
        const float4* src = reinterpret_cast<const float4*>(g_t + base);
        float4* dst = reinterpret_cast<float4*>(T1);
        for (int idx = tid; idx < N_ * C_ / 4; idx += 256) dst[idx] = src[idx];
    }
    {
        float4* dst = reinterpret_cast<float4*>(T2);
        for (int idx = tid; idx < N_ * C_ / 4; idx += 256) {
            int j = idx >> 5, q = idx & 31;
            const float4* src =
                reinterpret_cast<const float4*>(g_t + ((size_t)((b * N_ + j) * N_ + i)) * C_);
            dst[idx] = src[q];
        }
    }
    __syncthreads();

    const int warp = tid >> 5, lane = tid & 31;
    const int j0 = warp * 8;                  // warp owns rows j0..j0+7
    unsigned long long acc[8][4];             // packed (even-k, odd-k) partials
#pragma unroll
    for (int r = 0; r < 8; r++)
#pragma unroll
        for (int q = 0; q < 4; q++) acc[r][q] = 0ull;

    for (int k = 0; k < C_; k += 4) {
        ulonglong2 w0[4], w1[4];
#pragma unroll
        for (int q = 0; q < 4; q++) {
            int wo = (lane + 32 * q) * WSTRIDE + k;
            w0[q] = *reinterpret_cast<const ulonglong2*>(&Ws0[wo]);
            w1[q] = *reinterpret_cast<const ulonglong2*>(&Ws1[wo]);
        }
#pragma unroll
        for (int r = 0; r < 8; r++) {
            ulonglong2 t1 = *reinterpret_cast<const ulonglong2*>(&T1[(j0 + r) * C_ + k]);
            ulonglong2 t2 = *reinterpret_cast<const ulonglong2*>(&T2[(j0 + r) * C_ + k]);
#pragma unroll
            for (int q = 0; q < 4; q++) {
                acc[r][q] = ffma2(t1.x, w0[q].x, acc[r][q]);
                acc[r][q] = ffma2(t1.y, w0[q].y, acc[r][q]);
                acc[r][q] = ffma2(t2.x, w1[q].x, acc[r][q]);
                acc[r][q] = ffma2(t2.y, w1[q].y, acc[r][q]);
            }
        }
    }

    float add[4], dia[4];
#pragma unroll
    for (int q = 0; q < 4; q++) {
        int o = lane + 32 * q;
        add[q] = g_A[(size_t)p * C_ + o] + g_Cc[(size_t)b * C_ + o];
        dia[q] = g_D[(size_t)p * C_ + o] + g_Ec[(size_t)b * C_ + o];
    }
#pragma unroll
    for (int r = 0; r < 8; r++) {
        int j = j0 + r;
        const float* bvp = g_Bv + ((size_t)(b * N_ + j)) * C_;
        size_t ob = base + (size_t)j * C_;
#pragma unroll
        for (int q = 0; q < 4; q++) {
            int o = lane + 32 * q;
            float e = unpack_sum(acc[r][q]) + add[q] + bvp[o];
            if (j == i) e += dia[q];
            out[ob + o] = gelu_exact(e);
        }
    }
}

} // anonymous namespace

// ---------------- launch -----------------------------------------------------
extern "C" void kernel_launch(void* const* d_in, const int* in_sizes, int n_in,
                              void* d_out, int out_size) {
    const float* x   = (const float*)d_in[0];
    const float* Wi  = (const float*)d_in[3];
    const float* bi  = (const float*)d_in[4];
    const float* lg  = (const float*)d_in[5];
    const float* lb  = (const float*)d_in[6];
    const float* c00 = (const float*)d_in[7];
    const float* c01 = (const float*)d_in[8];
    const float* c10 = (const float*)d_in[9];
    const float* c11 = (const float*)d_in[10];
    float* out = (float*)d_out;

    const size_t smem_in   = (size_t)(C_ * WSTRIDE + N_ * C_ + C_) * sizeof(float);   // ~100.9 KB
    const size_t smem_abd  = (size_t)(3 * 32 * C_) * sizeof(float);                   // 48 KB
    const size_t smem_main = (size_t)(2 * C_ * WSTRIDE + 2 * N_ * C_) * sizeof(float);// ~200.7 KB
    cudaFuncSetAttribute(k_input, cudaFuncAttributeMaxDynamicSharedMemorySize, (int)smem_in);
    cudaFuncSetAttribute(k_abd,   cudaFuncAttributeMaxDynamicSharedMemorySize, (int)smem_abd);
    cudaFuncSetAttribute(k_main,  cudaFuncAttributeMaxDynamicSharedMemorySize, (int)smem_main);

    k_coeffs<<<(M_ * C_ * C_ + 255) / 256, 256>>>(c00, c01, c10, c11);
    k_input<<<B_ * N_, 256, smem_in>>>(x, Wi, bi, lg, lb);
    k_coldiag<<<B_ * N_, 128>>>();
    k_abd<<<64, 512, smem_abd>>>();
    k_ce<<<B_, 128>>>();
    k_main<<<B_ * N_, 256, smem_main>>>(out);   // launch #5 → ncu -s 5 captures this
}

// round 4
// speedup vs baseline: 1.2578x; 1.2491x over previous
#include <cuda_runtime.h>
#include <math.h>

namespace {

constexpr int B_ = 32;
constexpr int N_ = 64;
constexpr int C_ = 128;
constexpr int M_ = 15;
constexpr int E_ = B_ * N_ * N_;   // 131072
constexpr float LN_EPS = 1e-5f;
constexpr int WSTRIDE = 132;       // padded [o][k] stride

// ---------------- device scratch --------------------------------------------
__device__ __align__(16) float g_t[(size_t)E_ * C_];      // 64 MB post-LN activations
__device__ __align__(16) float g_row [B_ * N_ * C_];
__device__ __align__(16) float g_col [B_ * N_ * C_];
__device__ __align__(16) float g_diag[B_ * N_ * C_];
__device__ __align__(16) float g_A [B_ * N_ * C_];
__device__ __align__(16) float g_Bv[B_ * N_ * C_];
__device__ __align__(16) float g_D [B_ * N_ * C_];
__device__ __align__(16) float g_Cc[B_ * C_];
__device__ __align__(16) float g_Ec[B_ * C_];
__device__ __align__(16) float g_WT[M_ * C_ * C_];          // [m][c][o]
__device__ __align__(16) float g_Wpad[2 * C_ * WSTRIDE];    // maps 0,1 as [o][k] padded

union F2U { unsigned long long u; float2 f; };

__device__ __forceinline__ unsigned long long ffma2(unsigned long long a,
                                                    unsigned long long b,
                                                    unsigned long long c) {
    unsigned long long d;
    asm("fma.rn.f32x2 %0, %1, %2, %3;" : "=l"(d) : "l"(a), "l"(b), "l"(c));
    return d;
}
__device__ __forceinline__ float unpack_sum(unsigned long long u) {
    F2U x; x.u = u; return x.f.x + x.f.y;
}
__device__ __forceinline__ float gelu_exact(float v) {
    return 0.5f * v * (1.0f + erff(v * 0.70710678118654752440f));
}

// ---------------- K1: g_t = LN(GELU(x @ W_in^T + b)); fused row-mean --------
// Persistent: grid 296 (2 blocks/SM), each block strides over (b,i) tiles.
// Weights staged in smem ONCE per block.
__global__ void __launch_bounds__(256) k_input(
        const float* __restrict__ x, const float* __restrict__ Wi,
        const float* __restrict__ bi, const float* __restrict__ lg,
        const float* __restrict__ lb) {
    extern __shared__ float sm[];
    float* Ws = sm;                        // [128][132] W_in as [o][k], padded
    float* Xs = sm + C_ * WSTRIDE;         // [64][128] x tile
    float* rowsum = Xs + N_ * C_;          // [128]
    const int tid = threadIdx.x;
    const int warp = tid >> 5, lane = tid & 31;
    const int r0 = warp * 8;

    // Wi already [o][k]: copy rows into padded layout (once)
    for (int idx = tid; idx < C_ * (C_ / 4); idx += 256) {
        int o = idx >> 5, cq = idx & 31;
        *reinterpret_cast<float4*>(&Ws[o * WSTRIDE + cq * 4]) =
            *reinterpret_cast<const float4*>(&Wi[o * C_ + cq * 4]);
    }

    const float b0 = bi[lane], b1 = bi[lane + 32], b2 = bi[lane + 64], b3 = bi[lane + 96];
    const float lg0 = lg[lane], lg1 = lg[lane + 32], lg2 = lg[lane + 64], lg3 = lg[lane + 96];
    const float lb0 = lb[lane], lb1 = lb[lane + 32], lb2 = lb[lane + 64], lb3 = lb[lane + 96];
    int wo[4];
#pragma unroll
    for (int q = 0; q < 4; q++) wo[q] = (lane + 32 * q) * WSTRIDE;

    for (int p = blockIdx.x; p < B_ * N_; p += gridDim.x) {
        const size_t base = (size_t)p * (N_ * C_);
        __syncthreads();                    // prior tile fully consumed
        if (tid < C_) rowsum[tid] = 0.f;
        {
            const float4* src = reinterpret_cast<const float4*>(x + base);
            float4* dst = reinterpret_cast<float4*>(Xs);
            for (int idx = tid; idx < N_ * C_ / 4; idx += 256) dst[idx] = src[idx];
        }
        __syncthreads();

        unsigned long long acc[8][4];
#pragma unroll
        for (int r = 0; r < 8; r++)
#pragma unroll
            for (int q = 0; q < 4; q++) acc[r][q] = 0ull;

#pragma unroll 1
        for (int k = 0; k < C_; k += 4) {
            ulonglong2 w[4];
#pragma unroll
            for (int q = 0; q < 4; q++)
                w[q] = *reinterpret_cast<const ulonglong2*>(&Ws[wo[q] + k]);
            ulonglong2 a = *reinterpret_cast<const ulonglong2*>(&Xs[r0 * C_ + k]);
#pragma unroll
            for (int r = 0; r < 8; r++) {
                ulonglong2 nb;
                if (r < 7) nb = *reinterpret_cast<const ulonglong2*>(&Xs[(r0 + r + 1) * C_ + k]);
#pragma unroll
                for (int q = 0; q < 4; q++) {
                    acc[r][q] = ffma2(a.x, w[q].x, acc[r][q]);
                    acc[r][q] = ffma2(a.y, w[q].y, acc[r][q]);
                }
                a = nb;
            }
        }

        float rs0 = 0.f, rs1 = 0.f, rs2 = 0.f, rs3 = 0.f;
#pragma unroll
        for (int r = 0; r < 8; r++) {
            float v0 = gelu_exact(unpack_sum(acc[r][0]) + b0);
            float v1 = gelu_exact(unpack_sum(acc[r][1]) + b1);
            float v2 = gelu_exact(unpack_sum(acc[r][2]) + b2);
            float v3 = gelu_exact(unpack_sum(acc[r][3]) + b3);
            float s  = v0 + v1 + v2 + v3;
            float ss = v0 * v0 + v1 * v1 + v2 * v2 + v3 * v3;
#pragma unroll
            for (int off = 16; off; off >>= 1) {
                s  += __shfl_xor_sync(0xffffffffu, s,  off);
                ss += __shfl_xor_sync(0xffffffffu, ss, off);
            }
            float mu  = s * (1.0f / C_);
            float var = ss * (1.0f / C_) - mu * mu;
            float inv = rsqrtf(var + LN_EPS);
            float n0 = (v0 - mu) * inv * lg0 + lb0;
            float n1 = (v1 - mu) * inv * lg1 + lb1;
            float n2 = (v2 - mu) * inv * lg2 + lb2;
            float n3 = (v3 - mu) * inv * lg3 + lb3;
            size_t ob = base + (size_t)(r0 + r) * C_;
            g_t[ob + lane] = n0; g_t[ob + lane + 32] = n1;
            g_t[ob + lane + 64] = n2; g_t[ob + lane + 96] = n3;
            rs0 += n0; rs1 += n1; rs2 += n2; rs3 += n3;
        }
        atomicAdd(&rowsum[lane],      rs0);
        atomicAdd(&rowsum[lane + 32], rs1);
        atomicAdd(&rowsum[lane + 64], rs2);
        atomicAdd(&rowsum[lane + 96], rs3);
        __syncthreads();
        if (tid < C_) g_row[p * C_ + tid] = rowsum[tid] * (1.0f / N_);
    }
}

// ---------------- K2: coeffs + col means + diag (fused, independent parts) --
__global__ void __launch_bounds__(512) k_mix(
        const float* __restrict__ c00, const float* __restrict__ c01,
        const float* __restrict__ c10, const float* __restrict__ c11) {
    const int bx = blockIdx.x, tid = threadIdx.x;
    if (bx < 120) {       // coefficient build: 120*2048 = 245760 elems
#pragma unroll
        for (int u = 0; u < 4; u++) {
            int idx = bx * 2048 + u * 512 + tid;
            int o = idx & 127, c = (idx >> 7) & 127, m = idx >> 14;
            float v = c00[o * M_ + m] * c10[o * C_ + c] + c01[c * M_ + m] * c11[o * C_ + c];
            g_WT[idx] = v;
            if (m < 2) g_Wpad[m * C_ * WSTRIDE + o * WSTRIDE + c] = v;
        }
    } else {              // col means + diag: 512 blocks x 4 (b,q) each
        int p = (bx - 120) * 4 + (tid >> 7);
        int c = tid & 127;
        int b = p >> 6, q = p & 63;
        float s = 0.f;
        const size_t stride = (size_t)N_ * C_;
        size_t baseq = (size_t)(b * N_ * N_) * C_ + (size_t)q * C_ + c;
#pragma unroll 4
        for (int i2 = 0; i2 < N_; i2++) s += g_t[baseq + (size_t)i2 * stride];
        g_col[p * C_ + c] = s * (1.0f / N_);
        g_diag[p * C_ + c] = g_t[((size_t)((b * N_ + q) * N_ + q)) * C_ + c];
    }
}

// ---------------- K3: A,Bv,D (maps 2..7,10..12) + Cc,Ec (8,9,13,14) ---------
__global__ void __launch_bounds__(512) k_abd_ce() {
    const int tid = threadIdx.x;
    if (blockIdx.x < 128) {
        __shared__ float s_in[3 * 16 * C_];        // diag | row | col, 16 rows
        float* sd = s_in;
        float* sr = s_in + 16 * C_;
        float* sc = s_in + 32 * C_;
        const int rb = blockIdx.x * 16;
        for (int idx = tid; idx < 16 * C_; idx += 512) {
            sd[idx] = g_diag[rb * C_ + idx];
            sr[idx] = g_row [rb * C_ + idx];
            sc[idx] = g_col [rb * C_ + idx];
        }
        __syncthreads();
        const int o = tid & 127, grp = tid >> 7;   // 4 groups x 4 rows
        const float* W[9] = {
            g_WT + 2 * C_ * C_, g_WT + 4 * C_ * C_, g_WT + 6 * C_ * C_,   // A
            g_WT + 3 * C_ * C_, g_WT + 5 * C_ * C_, g_WT + 7 * C_ * C_,   // Bv
            g_WT + 10 * C_ * C_, g_WT + 11 * C_ * C_, g_WT + 12 * C_ * C_ // D
        };
        float acc[4][3];
#pragma unroll
        for (int r = 0; r < 4; r++) { acc[r][0] = acc[r][1] = acc[r][2] = 0.f; }
#pragma unroll 1
        for (int c0 = 0; c0 < C_; c0 += 4) {
            float w[4][9];
#pragma unroll
            for (int u = 0; u < 4; u++) {
                int wi = (c0 + u) * C_ + o;
#pragma unroll
                for (int m = 0; m < 9; m++) w[u][m] = W[m][wi];
            }
#pragma unroll
            for (int u = 0; u < 4; u++) {
                int c = c0 + u;
#pragma unroll
                for (int r = 0; r < 4; r++) {
                    int rr = grp * 4 + r;
                    float d = sd[rr * C_ + c], ro = sr[rr * C_ + c], co = sc[rr * C_ + c];
                    acc[r][0] = fmaf(w[u][0], d, fmaf(w[u][1], ro, fmaf(w[u][2], co, acc[r][0])));
                    acc[r][1] = fmaf(w[u][3], d, fmaf(w[u][4], ro, fmaf(w[u][5], co, acc[r][1])));
                    acc[r][2] = fmaf(w[u][6], d, fmaf(w[u][7], ro, fmaf(w[u][8], co, acc[r][2])));
                }
            }
        }
#pragma unroll
        for (int r = 0; r < 4; r++) {
            int rr = rb + grp * 4 + r;
            g_A [rr * C_ + o] = acc[r][0];
            g_Bv[rr * C_ + o] = acc[r][1];
            g_D [rr * C_ + o] = acc[r][2];
        }
    } else {   // Cc / Ec: 32 blocks, one per batch
        __shared__ float str[C_], sto[C_], red[8][C_];
        const int b = blockIdx.x - 128;
        if (tid < C_) {
            float st = 0.f, so = 0.f;
#pragma unroll 4
            for (int q = 0; q < N_; q++) {
                st += g_diag[(b * N_ + q) * C_ + tid];
                so += g_row [(b * N_ + q) * C_ + tid];
            }
            str[tid] = st * (1.0f / N_);
            sto[tid] = so * (1.0f / N_);
        }
        __syncthreads();
        const int o = tid & 127, grp = tid >> 7;
        const float* W8  = g_WT + 8  * C_ * C_;
        const float* W9  = g_WT + 9  * C_ * C_;
        const float* W13 = g_WT + 13 * C_ * C_;
        const float* W14 = g_WT + 14 * C_ * C_;
        float a = 0.f, e = 0.f;
        for (int c = grp * 32; c < grp * 32 + 32; c++) {
            int wi = c * C_ + o;
            float tr = str[c], to = sto[c];
            a = fmaf(W8 [wi], tr, fmaf(W9 [wi], to, a));
            e = fmaf(W13[wi], tr, fmaf(W14[wi], to, e));
        }
        red[grp][o] = a; red[4 + grp][o] = e;
        __syncthreads();
        if (tid < C_) {
            g_Cc[b * C_ + tid] = red[0][tid] + red[1][tid] + red[2][tid] + red[3][tid];
            g_Ec[b * C_ + tid] = red[4][tid] + red[5][tid] + red[6][tid] + red[7][tid];
        }
    }
}

// ---------------- K4: main GEMM pair + broadcasts + GELU --------------------
// Persistent: grid 148 (1 block/SM), weights in smem once; pipelined mainloop.
__global__ void __launch_bounds__(256) k_main(float* __restrict__ out) {
    extern __shared__ float sm[];
    float* Ws0 = sm;                         // [128][132]
    float* Ws1 = Ws0 + C_ * WSTRIDE;
    float* T1  = Ws1 + C_ * WSTRIDE;         // [64][128]
    float* T2  = T1 + N_ * C_;               // [64][128]
    const int tid = threadIdx.x;
    const int warp = tid >> 5, lane = tid & 31;
    const int j0 = warp * 8;

    {   // weights once: linear copy of both padded maps
        const float4* src = reinterpret_cast<const float4*>(g_Wpad);
        float4* dst = reinterpret_cast<float4*>(Ws0);
        for (int idx = tid; idx < 2 * C_ * WSTRIDE / 4; idx += 256) dst[idx] = src[idx];
    }
    int wo[4];
#pragma unroll
    for (int q = 0; q < 4; q++) wo[q] = (lane + 32 * q) * WSTRIDE;

    for (int p = blockIdx.x; p < B_ * N_; p += gridDim.x) {
        const int b = p >> 6, i = p & 63;
        const size_t base = (size_t)p * (N_ * C_);
        __syncthreads();                     // prior tile consumed (covers Ws copy too)
        {
            const float4* src = reinterpret_cast<const float4*>(g_t + base);
            float4* dst = reinterpret_cast<float4*>(T1);
            for (int idx = tid; idx < N_ * C_ / 4; idx += 256) dst[idx] = src[idx];
        }
        {
            float4* dst = reinterpret_cast<float4*>(T2);
            for (int idx = tid; idx < N_ * C_ / 4; idx += 256) {
                int j = idx >> 5, q = idx & 31;
                const float4* src =
                    reinterpret_cast<const float4*>(g_t + ((size_t)((b * N_ + j) * N_ + i)) * C_);
                dst[idx] = src[q];
            }
        }
        __syncthreads();

        unsigned long long acc[8][4];
#pragma unroll
        for (int r = 0; r < 8; r++)
#pragma unroll
            for (int q = 0; q < 4; q++) acc[r][q] = 0ull;

        ulonglong2 w0c[4], w1c[4];
#pragma unroll
        for (int q = 0; q < 4; q++) {
            w0c[q] = *reinterpret_cast<const ulonglong2*>(&Ws0[wo[q]]);
            w1c[q] = *reinterpret_cast<const ulonglong2*>(&Ws1[wo[q]]);
        }
#pragma unroll 1
        for (int k = 0; k < C_; k += 4) {
            const int kn = (k + 4 < C_) ? k + 4 : 0;   // clamped prefetch addr
            ulonglong2 w0n[4], w1n[4];
#pragma unroll
            for (int q = 0; q < 4; q++) {
                w0n[q] = *reinterpret_cast<const ulonglong2*>(&Ws0[wo[q] + kn]);
                w1n[q] = *reinterpret_cast<const ulonglong2*>(&Ws1[wo[q] + kn]);
            }
            ulonglong2 a1 = *reinterpret_cast<const ulonglong2*>(&T1[j0 * C_ + k]);
            ulonglong2 a2 = *reinterpret_cast<const ulonglong2*>(&T2[j0 * C_ + k]);
#pragma unroll
            for (int r = 0; r < 8; r++) {
                ulonglong2 b1, b2;
                if (r < 7) {
                    b1 = *reinterpret_cast<const ulonglong2*>(&T1[(j0 + r + 1) * C_ + k]);
                    b2 = *reinterpret_cast<const ulonglong2*>(&T2[(j0 + r + 1) * C_ + k]);
                }
#pragma unroll
                for (int q = 0; q < 4; q++) {
                    acc[r][q] = ffma2(a1.x, w0c[q].x, acc[r][q]);
                    acc[r][q] = ffma2(a1.y, w0c[q].y, acc[r][q]);
                    acc[r][q] = ffma2(a2.x, w1c[q].x, acc[r][q]);
                    acc[r][q] = ffma2(a2.y, w1c[q].y, acc[r][q]);
                }
                a1 = b1; a2 = b2;
            }
#pragma unroll
            for (int q = 0; q < 4; q++) { w0c[q] = w0n[q]; w1c[q] = w1n[q]; }
        }

        float add[4], dia[4];
#pragma unroll
        for (int q = 0; q < 4; q++) {
            int o = lane + 32 * q;
            add[q] = g_A[(size_t)p * C_ + o] + g_Cc[(size_t)b * C_ + o];
            dia[q] = g_D[(size_t)p * C_ + o] + g_Ec[(size_t)b * C_ + o];
        }
#pragma unroll
        for (int r = 0; r < 8; r++) {
            int j = j0 + r;
            const float* bvp = g_Bv + ((size_t)(b * N_ + j)) * C_;
            size_t ob = base + (size_t)j * C_;
#pragma unroll
            for (int q = 0; q < 4; q++) {
                int o = lane + 32 * q;
                float e = unpack_sum(acc[r][q]) + add[q] + bvp[o];
                if (j == i) e += dia[q];
                out[ob + o] = gelu_exact(e);
            }
        }
    }
}

} // anonymous namespace

// ---------------- launch -----------------------------------------------------
extern "C" void kernel_launch(void* const* d_in, const int* in_sizes, int n_in,
                              void* d_out, int out_size) {
    const float* x   = (const float*)d_in[0];
    const float* Wi  = (const float*)d_in[3];
    const float* bi  = (const float*)d_in[4];
    const float* lg  = (const float*)d_in[5];
    const float* lb  = (const float*)d_in[6];
    const float* c00 = (const float*)d_in[7];
    const float* c01 = (const float*)d_in[8];
    const float* c10 = (const float*)d_in[9];
    const float* c11 = (const float*)d_in[10];
    float* out = (float*)d_out;

    const size_t smem_in   = (size_t)(C_ * WSTRIDE + N_ * C_ + C_) * sizeof(float);    // ~101 KB
    const size_t smem_main = (size_t)(2 * C_ * WSTRIDE + 2 * N_ * C_) * sizeof(float); // ~201 KB
    cudaFuncSetAttribute(k_input, cudaFuncAttributeMaxDynamicSharedMemorySize, (int)smem_in);
    cudaFuncSetAttribute(k_main,  cudaFuncAttributeMaxDynamicSharedMemorySize, (int)smem_main);

    k_input <<<296, 256, smem_in>>>(x, Wi, bi, lg, lb);   // persistent, 2 blocks/SM
    k_mix   <<<632, 512>>>(c00, c01, c10, c11);           // coeffs + col/diag
    k_abd_ce<<<160, 512>>>();                             // A,Bv,D + Cc,Ec
    k_main  <<<148, 256, smem_main>>>(out);               // persistent, 1 block/SM (4th launch → ncu)
}

// round 6
// speedup vs baseline: 1.9175x; 1.5245x over previous
#include <cuda_runtime.h>
#include <cuda_bf16.h>
#include <math.h>
#include <stdint.h>

namespace {

constexpr int B_ = 32;
constexpr int N_ = 64;
constexpr int C_ = 128;
constexpr int M_ = 15;
constexpr int E_ = B_ * N_ * N_;   // 131072
constexpr float LN_EPS = 1e-5f;
constexpr int WSTRIDE = 132;       // padded [o][k] fp32 stride for k_input
constexpr int TSTR = 136;          // padded bf16 row stride (272B: conflict-free ldmatrix)
constexpr int WSEG = 128 * TSTR;   // elements per weight segment

// ---------------- device scratch --------------------------------------------
__device__ __align__(16) float g_t[(size_t)E_ * C_];      // 64 MB post-LN activations
__device__ __align__(16) float g_row [B_ * N_ * C_];
__device__ __align__(16) float g_col [B_ * N_ * C_];
__device__ __align__(16) float g_diag[B_ * N_ * C_];
__device__ __align__(16) float g_A [B_ * N_ * C_];
__device__ __align__(16) float g_Bv[B_ * N_ * C_];
__device__ __align__(16) float g_D [B_ * N_ * C_];
__device__ __align__(16) float g_Cc[B_ * C_];
__device__ __align__(16) float g_Ec[B_ * C_];
__device__ __align__(16) float g_WT[M_ * C_ * C_];          // [m][c][o] (small projections)
// maps 0,1 split bf16, padded [o][k] stride 136: segs {W0hi, W0lo, W1hi, W1lo}
__device__ __align__(16) __nv_bfloat16 g_Wb[4 * WSEG];

// ---------------- helpers ----------------------------------------------------
union F2U { unsigned long long u; float2 f; };
__device__ __forceinline__ unsigned long long ffma2(unsigned long long a,
                                                    unsigned long long b,
                                                    unsigned long long c) {
    unsigned long long d;
    asm("fma.rn.f32x2 %0, %1, %2, %3;" : "=l"(d) : "l"(a), "l"(b), "l"(c));
    return d;
}
__device__ __forceinline__ float unpack_sum(unsigned long long u) {
    F2U x; x.u = u; return x.f.x + x.f.y;
}
__device__ __forceinline__ float gelu_exact(float v) {
    return 0.5f * v * (1.0f + erff(v * 0.70710678118654752440f));
}
__device__ __forceinline__ uint32_t smem_to_u32(const void* p) {
    uint32_t a;
    asm("{ .reg .u64 t; cvta.to.shared.u64 t, %1; cvt.u32.u64 %0, t; }" : "=r"(a) : "l"(p));
    return a;
}
__device__ __forceinline__ void ldsm4(uint32_t* r, uint32_t addr) {
    asm volatile("ldmatrix.sync.aligned.m8n8.x4.shared.b16 {%0,%1,%2,%3}, [%4];"
                 : "=r"(r[0]), "=r"(r[1]), "=r"(r[2]), "=r"(r[3]) : "r"(addr));
}
__device__ __forceinline__ void mma16816(float* d, const uint32_t* a,
                                         uint32_t b0, uint32_t b1) {
    asm volatile("mma.sync.aligned.m16n8k16.row.col.f32.bf16.bf16.f32 "
                 "{%0,%1,%2,%3}, {%4,%5,%6,%7}, {%8,%9}, {%0,%1,%2,%3};"
                 : "+f"(d[0]), "+f"(d[1]), "+f"(d[2]), "+f"(d[3])
                 : "r"(a[0]), "r"(a[1]), "r"(a[2]), "r"(a[3]), "r"(b0), "r"(b1));
}
// split one float4 into hi/lo bf16x2 pairs
__device__ __forceinline__ void cvt_split4(float4 v, uint2& h, uint2& l) {
    __nv_bfloat162 h0 = __floats2bfloat162_rn(v.x, v.y);
    __nv_bfloat162 h1 = __floats2bfloat162_rn(v.z, v.w);
    float r0 = v.x - __bfloat162float(h0.x);
    float r1 = v.y - __bfloat162float(h0.y);
    float r2 = v.z - __bfloat162float(h1.x);
    float r3 = v.w - __bfloat162float(h1.y);
    __nv_bfloat162 l0 = __floats2bfloat162_rn(r0, r1);
    __nv_bfloat162 l1 = __floats2bfloat162_rn(r2, r3);
    h.x = *reinterpret_cast<uint32_t*>(&h0); h.y = *reinterpret_cast<uint32_t*>(&h1);
    l.x = *reinterpret_cast<uint32_t*>(&l0); l.y = *reinterpret_cast<uint32_t*>(&l1);
}

// ---------------- K1: g_t = LN(GELU(x @ W_in^T + b)); fused row-mean --------
__global__ void __launch_bounds__(256) k_input(
        const float* __restrict__ x, const float* __restrict__ Wi,
        const float* __restrict__ bi, const float* __restrict__ lg,
        const float* __restrict__ lb) {
    extern __shared__ float sm[];
    float* Ws = sm;                        // [128][132]
    float* Xs = sm + C_ * WSTRIDE;         // [64][128]
    float* rowsum = Xs + N_ * C_;          // [128]
    const int tid = threadIdx.x;
    const int warp = tid >> 5, lane = tid & 31;
    const int r0 = warp * 8;

    for (int idx = tid; idx < C_ * (C_ / 4); idx += 256) {
        int o = idx >> 5, cq = idx & 31;
        *reinterpret_cast<float4*>(&Ws[o * WSTRIDE + cq * 4]) =
            *reinterpret_cast<const float4*>(&Wi[o * C_ + cq * 4]);
    }

    const float b0 = bi[lane], b1 = bi[lane + 32], b2 = bi[lane + 64], b3 = bi[lane + 96];
    const float lg0 = lg[lane], lg1 = lg[lane + 32], lg2 = lg[lane + 64], lg3 = lg[lane + 96];
    const float lb0 = lb[lane], lb1 = lb[lane + 32], lb2 = lb[lane + 64], lb3 = lb[lane + 96];
    int wo[4];
#pragma unroll
    for (int q = 0; q < 4; q++) wo[q] = (lane + 32 * q) * WSTRIDE;

    for (int p = blockIdx.x; p < B_ * N_; p += gridDim.x) {
        const size_t base = (size_t)p * (N_ * C_);
        __syncthreads();
        if (tid < C_) rowsum[tid] = 0.f;
        {
            const float4* src = reinterpret_cast<const float4*>(x + base);
            float4* dst = reinterpret_cast<float4*>(Xs);
            for (int idx = tid; idx < N_ * C_ / 4; idx += 256) dst[idx] = src[idx];
        }
        __syncthreads();

        unsigned long long acc[8][4];
#pragma unroll
        for (int r = 0; r < 8; r++)
#pragma unroll
            for (int q = 0; q < 4; q++) acc[r][q] = 0ull;

#pragma unroll 1
        for (int k = 0; k < C_; k += 4) {
            ulonglong2 w[4];
#pragma unroll
            for (int q = 0; q < 4; q++)
                w[q] = *reinterpret_cast<const ulonglong2*>(&Ws[wo[q] + k]);
            ulonglong2 a = *reinterpret_cast<const ulonglong2*>(&Xs[r0 * C_ + k]);
#pragma unroll
            for (int r = 0; r < 8; r++) {
                ulonglong2 nb;
                if (r < 7) nb = *reinterpret_cast<const ulonglong2*>(&Xs[(r0 + r + 1) * C_ + k]);
#pragma unroll
                for (int q = 0; q < 4; q++) {
                    acc[r][q] = ffma2(a.x, w[q].x, acc[r][q]);
                    acc[r][q] = ffma2(a.y, w[q].y, acc[r][q]);
                }
                a = nb;
            }
        }

        float rs0 = 0.f, rs1 = 0.f, rs2 = 0.f, rs3 = 0.f;
#pragma unroll
        for (int r = 0; r < 8; r++) {
            float v0 = gelu_exact(unpack_sum(acc[r][0]) + b0);
            float v1 = gelu_exact(unpack_sum(acc[r][1]) + b1);
            float v2 = gelu_exact(unpack_sum(acc[r][2]) + b2);
            float v3 = gelu_exact(unpack_sum(acc[r][3]) + b3);
            float s  = v0 + v1 + v2 + v3;
            float ss = v0 * v0 + v1 * v1 + v2 * v2 + v3 * v3;
#pragma unroll
            for (int off = 16; off; off >>= 1) {
                s  += __shfl_xor_sync(0xffffffffu, s,  off);
                ss += __shfl_xor_sync(0xffffffffu, ss, off);
            }
            float mu  = s * (1.0f / C_);
            float var = ss * (1.0f / C_) - mu * mu;
            float inv = rsqrtf(var + LN_EPS);
            float n0 = (v0 - mu) * inv * lg0 + lb0;
            float n1 = (v1 - mu) * inv * lg1 + lb1;
            float n2 = (v2 - mu) * inv * lg2 + lb2;
            float n3 = (v3 - mu) * inv * lg3 + lb3;
            size_t ob = base + (size_t)(r0 + r) * C_;
            g_t[ob + lane] = n0; g_t[ob + lane + 32] = n1;
            g_t[ob + lane + 64] = n2; g_t[ob + lane + 96] = n3;
            rs0 += n0; rs1 += n1; rs2 += n2; rs3 += n3;
        }
        atomicAdd(&rowsum[lane],      rs0);
        atomicAdd(&rowsum[lane + 32], rs1);
        atomicAdd(&rowsum[lane + 64], rs2);
        atomicAdd(&rowsum[lane + 96], rs3);
        __syncthreads();
        if (tid < C_) g_row[p * C_ + tid] = rowsum[tid] * (1.0f / N_);
    }
}

// ---------------- K2: coeffs (+ split bf16 W0/W1) + col means + diag --------
__global__ void __launch_bounds__(512) k_mix(
        const float* __restrict__ c00, const float* __restrict__ c01,
        const float* __restrict__ c10, const float* __restrict__ c11) {
    const int bx = blockIdx.x, tid = threadIdx.x;
    if (bx < 120) {
#pragma unroll
        for (int u = 0; u < 4; u++) {
            int idx = bx * 2048 + u * 512 + tid;
            int o = idx & 127, c = (idx >> 7) & 127, m = idx >> 14;
            float v = c00[o * M_ + m] * c10[o * C_ + c] + c01[c * M_ + m] * c11[o * C_ + c];
            g_WT[idx] = v;
            if (m < 2) {
                __nv_bfloat16 hb = __float2bfloat16_rn(v);
                float rr = v - __bfloat162float(hb);
                __nv_bfloat16 lo = __float2bfloat16_rn(rr);
                g_Wb[(m * 2 + 0) * WSEG + o * TSTR + c] = hb;
                g_Wb[(m * 2 + 1) * WSEG + o * TSTR + c] = lo;
            }
        }
    } else {
        int p = (bx - 120) * 4 + (tid >> 7);
        int c = tid & 127;
        int b = p >> 6, q = p & 63;
        float s = 0.f;
        const size_t stride = (size_t)N_ * C_;
        size_t baseq = (size_t)(b * N_ * N_) * C_ + (size_t)q * C_ + c;
#pragma unroll 4
        for (int i2 = 0; i2 < N_; i2++) s += g_t[baseq + (size_t)i2 * stride];
        g_col[p * C_ + c] = s * (1.0f / N_);
        g_diag[p * C_ + c] = g_t[((size_t)((b * N_ + q) * N_ + q)) * C_ + c];
    }
}

// ---------------- K3: A,Bv,D + Cc,Ec ----------------------------------------
__global__ void __launch_bounds__(512) k_abd_ce() {
    const int tid = threadIdx.x;
    if (blockIdx.x < 128) {
        __shared__ float s_in[3 * 16 * C_];
        float* sd = s_in;
        float* sr = s_in + 16 * C_;
        float* sc = s_in + 32 * C_;
        const int rb = blockIdx.x * 16;
        for (int idx = tid; idx < 16 * C_; idx += 512) {
            sd[idx] = g_diag[rb * C_ + idx];
            sr[idx] = g_row [rb * C_ + idx];
            sc[idx] = g_col [rb * C_ + idx];
        }
        __syncthreads();
        const int o = tid & 127, grp = tid >> 7;
        const float* W[9] = {
            g_WT + 2 * C_ * C_, g_WT + 4 * C_ * C_, g_WT + 6 * C_ * C_,
            g_WT + 3 * C_ * C_, g_WT + 5 * C_ * C_, g_WT + 7 * C_ * C_,
            g_WT + 10 * C_ * C_, g_WT + 11 * C_ * C_, g_WT + 12 * C_ * C_
        };
        float acc[4][3];
#pragma unroll
        for (int r = 0; r < 4; r++) { acc[r][0] = acc[r][1] = acc[r][2] = 0.f; }
#pragma unroll 1
        for (int c0 = 0; c0 < C_; c0 += 4) {
            float w[4][9];
#pragma unroll
            for (int u = 0; u < 4; u++) {
                int wi = (c0 + u) * C_ + o;
#pragma unroll
                for (int m = 0; m < 9; m++) w[u][m] = W[m][wi];
            }
#pragma unroll
            for (int u = 0; u < 4; u++) {
                int c = c0 + u;
#pragma unroll
                for (int r = 0; r < 4; r++) {
                    int rr = grp * 4 + r;
                    float d = sd[rr * C_ + c], ro = sr[rr * C_ + c], co = sc[rr * C_ + c];
                    acc[r][0] = fmaf(w[u][0], d, fmaf(w[u][1], ro, fmaf(w[u][2], co, acc[r][0])));
                    acc[r][1] = fmaf(w[u][3], d, fmaf(w[u][4], ro, fmaf(w[u][5], co, acc[r][1])));
                    acc[r][2] = fmaf(w[u][6], d, fmaf(w[u][7], ro, fmaf(w[u][8], co, acc[r][2])));
                }
            }
        }
#pragma unroll
        for (int r = 0; r < 4; r++) {
            int rr = rb + grp * 4 + r;
            g_A [rr * C_ + o] = acc[r][0];
            g_Bv[rr * C_ + o] = acc[r][1];
            g_D [rr * C_ + o] = acc[r][2];
        }
    } else {
        __shared__ float str[C_], sto[C_], red[8][C_];
        const int b = blockIdx.x - 128;
        if (tid < C_) {
            float st = 0.f, so = 0.f;
#pragma unroll 4
            for (int q = 0; q < N_; q++) {
                st += g_diag[(b * N_ + q) * C_ + tid];
                so += g_row [(b * N_ + q) * C_ + tid];
            }
            str[tid] = st * (1.0f / N_);
            sto[tid] = so * (1.0f / N_);
        }
        __syncthreads();
        const int o = tid & 127, grp = tid >> 7;
        const float* W8  = g_WT + 8  * C_ * C_;
        const float* W9  = g_WT + 9  * C_ * C_;
        const float* W13 = g_WT + 13 * C_ * C_;
        const float* W14 = g_WT + 14 * C_ * C_;
        float a = 0.f, e = 0.f;
        for (int c = grp * 32; c < grp * 32 + 32; c++) {
            int wi = c * C_ + o;
            float tr = str[c], to = sto[c];
            a = fmaf(W8 [wi], tr, fmaf(W9 [wi], to, a));
            e = fmaf(W13[wi], tr, fmaf(W14[wi], to, e));
        }
        red[grp][o] = a; red[4 + grp][o] = e;
        __syncthreads();
        if (tid < C_) {
            g_Cc[b * C_ + tid] = red[0][tid] + red[1][tid] + red[2][tid] + red[3][tid];
            g_Ec[b * C_ + tid] = red[4][tid] + red[5][tid] + red[6][tid] + red[7][tid];
        }
    }
}

// ---------------- K4: warp-MMA main GEMM pair + broadcasts + GELU -----------
// Persistent, grid=148, 256 threads. Per (b,i) tile:
//   D[64j][128o] = T1·W0hi+lo-split + T2·W1  via mma.sync m16n8k16 bf16.
// smem bytes: W segs 4x34816 @0; T segs 4x17408 @139264. Total 208896.
constexpr int SMB_W0H = 0;
constexpr int SMB_W0L = 34816;
constexpr int SMB_W1H = 69632;
constexpr int SMB_W1L = 104448;
constexpr int SMB_T1H = 139264;
constexpr int SMB_T1L = 156672;
constexpr int SMB_T2H = 174080;
constexpr int SMB_T2L = 191488;
constexpr int SM_MAIN = 208896;

__global__ void __launch_bounds__(256) k_main(float* __restrict__ out) {
    extern __shared__ __align__(16) unsigned char smem[];
    const uint32_t sb = smem_to_u32(smem);
    const int tid = threadIdx.x, wid = tid >> 5, lane = tid & 31;
    const int j0 = (wid & 3) * 16;          // warp's 16 j-rows
    const int nh = wid >> 2;                // warp's 64-o half

    {   // stage split weights once per block (prepacked layout, linear copy)
        const uint4* src = reinterpret_cast<const uint4*>(g_Wb);
        uint4* dst = reinterpret_cast<uint4*>(smem);
        for (int i = tid; i < 4 * WSEG * 2 / 16; i += 256) dst[i] = src[i];
    }

    // per-lane ldmatrix address components (element offsets within a tile)
    const uint32_t a_off = (uint32_t)((lane & 15) * TSTR + ((lane >> 4) << 3)) * 2;
    const uint32_t b_off = (uint32_t)((((lane >> 4) << 3) + (lane & 7)) * TSTR
                                      + (((lane >> 3) & 1) << 3)) * 2;

    for (int p = blockIdx.x; p < B_ * N_; p += gridDim.x) {
        const int b = p >> 6, i = p & 63;
        __syncthreads();                    // prior tile's MMA reads done
        // ---- stage T1 (contiguous rows) and T2 (transposed gather) ----
        {
            const float* s1 = g_t + (size_t)p * (N_ * C_);
#pragma unroll 1
            for (int u = 0; u < 8; u++) {
                int idx = u * 256 + tid;          // 0..2047
                int r = idx >> 5, c4 = (idx & 31) * 4;
                uint32_t so = (uint32_t)(r * TSTR + c4) * 2;
                float4 v1 = *reinterpret_cast<const float4*>(s1 + r * C_ + c4);
                uint2 h, l;
                cvt_split4(v1, h, l);
                *reinterpret_cast<uint2*>(smem + SMB_T1H + so) = h;
                *reinterpret_cast<uint2*>(smem + SMB_T1L + so) = l;
                const float* s2 = g_t + ((size_t)((b * N_ + r) * N_ + i)) * C_;
                float4 v2 = *reinterpret_cast<const float4*>(s2 + c4);
                cvt_split4(v2, h, l);
                *reinterpret_cast<uint2*>(smem + SMB_T2H + so) = h;
                *reinterpret_cast<uint2*>(smem + SMB_T2L + so) = l;
            }
        }
        __syncthreads();

        // ---- MMA mainloop ----
        float acc[8][4];
#pragma unroll
        for (int nt = 0; nt < 8; nt++)
#pragma unroll
            for (int q = 0; q < 4; q++) acc[nt][q] = 0.f;

#pragma unroll 1
        for (int kt = 0; kt < 8; kt++) {
            const uint32_t kb = kt * 16 * 2;             // byte offset of k-base
            const uint32_t arow = (uint32_t)(j0 * TSTR) * 2 + a_off + kb;
            uint32_t a1h[4], a1l[4], a2h[4], a2l[4];
            ldsm4(a1h, sb + SMB_T1H + arow);
            ldsm4(a1l, sb + SMB_T1L + arow);
            ldsm4(a2h, sb + SMB_T2H + arow);
            ldsm4(a2l, sb + SMB_T2L + arow);
#pragma unroll
            for (int np = 0; np < 4; np++) {             // nt pair {2np, 2np+1}
                const uint32_t brow =
                    (uint32_t)((nh * 64 + np * 16) * TSTR) * 2 + b_off + kb;
                uint32_t w0h[4], w0l[4], w1h[4], w1l[4];
                ldsm4(w0h, sb + SMB_W0H + brow);
                ldsm4(w0l, sb + SMB_W0L + brow);
                ldsm4(w1h, sb + SMB_W1H + brow);
                ldsm4(w1l, sb + SMB_W1L + brow);
#pragma unroll
                for (int e = 0; e < 2; e++) {            // nt = 2np + e
                    float* d = acc[np * 2 + e];
                    const int rg = e * 2;                // B frag regs {rg, rg+1}
                    mma16816(d, a1h, w0h[rg], w0h[rg + 1]);
                    mma16816(d, a1h, w0l[rg], w0l[rg + 1]);
                    mma16816(d, a1l, w0h[rg], w0h[rg + 1]);
                    mma16816(d, a2h, w1h[rg], w1h[rg + 1]);
                    mma16816(d, a2h, w1l[rg], w1l[rg + 1]);
                    mma16816(d, a2l, w1h[rg], w1h[rg + 1]);
                }
            }
        }

        // ---- epilogue: broadcasts + GELU + store ----
        {
            const int rg = lane >> 2;            // row group within m-tile
            const int c2 = (lane & 3) * 2;       // col pair within n-tile
            const int ja = j0 + rg, jb = j0 + rg + 8;
            const float* Ap  = g_A  + (size_t)p * C_;
            const float* Ccp = g_Cc + (size_t)b * C_;
            const float* Dp  = g_D  + (size_t)p * C_;
            const float* Ep  = g_Ec + (size_t)b * C_;
            const float* Bva = g_Bv + ((size_t)(b * N_ + ja)) * C_;
            const float* Bvb = g_Bv + ((size_t)(b * N_ + jb)) * C_;
            float* outa = out + ((size_t)p * N_ + ja) * C_;
            float* outb = out + ((size_t)p * N_ + jb) * C_;
            const bool da = (ja == i), db = (jb == i);
#pragma unroll
            for (int nt = 0; nt < 8; nt++) {
                const int o = nh * 64 + nt * 8 + c2;
                float2 av = *reinterpret_cast<const float2*>(Ap + o);
                float2 cv = *reinterpret_cast<const float2*>(Ccp + o);
                const float addx = av.x + cv.x, addy = av.y + cv.y;
                float2 dd, ee;
                if (da || db) {
                    dd = *reinterpret_cast<const float2*>(Dp + o);
                    ee = *reinterpret_cast<const float2*>(Ep + o);
                }
                {
                    float2 bv = *reinterpret_cast<const float2*>(Bva + o);
                    float e0 = acc[nt][0] + addx + bv.x;
                    float e1 = acc[nt][1] + addy + bv.y;
                    if (da) { e0 += dd.x + ee.x; e1 += dd.y + ee.y; }
                    float2 o2; o2.x = gelu_exact(e0); o2.y = gelu_exact(e1);
                    *reinterpret_cast<float2*>(outa + o) = o2;
                }
                {
                    float2 bv = *reinterpret_cast<const float2*>(Bvb + o);
                    float e0 = acc[nt][2] + addx + bv.x;
                    float e1 = acc[nt][3] + addy + bv.y;
                    if (db) { e0 += dd.x + ee.x; e1 += dd.y + ee.y; }
                    float2 o2; o2.x = gelu_exact(e0); o2.y = gelu_exact(e1);
                    *reinterpret_cast<float2*>(outb + o) = o2;
                }
            }
        }
    }
}

} // anonymous namespace

// ---------------- launch -----------------------------------------------------
extern "C" void kernel_launch(void* const* d_in, const int* in_sizes, int n_in,
                              void* d_out, int out_size) {
    const float* x   = (const float*)d_in[0];
    const float* Wi  = (const float*)d_in[3];
    const float* bi  = (const float*)d_in[4];
    const float* lg  = (const float*)d_in[5];
    const float* lb  = (const float*)d_in[6];
    const float* c00 = (const float*)d_in[7];
    const float* c01 = (const float*)d_in[8];
    const float* c10 = (const float*)d_in[9];
    const float* c11 = (const float*)d_in[10];
    float* out = (float*)d_out;

    const size_t smem_in = (size_t)(C_ * WSTRIDE + N_ * C_ + C_) * sizeof(float);  // ~101 KB
    cudaFuncSetAttribute(k_input, cudaFuncAttributeMaxDynamicSharedMemorySize, (int)smem_in);
    cudaFuncSetAttribute(k_main,  cudaFuncAttributeMaxDynamicSharedMemorySize, SM_MAIN);

    k_input <<<296, 256, smem_in>>>(x, Wi, bi, lg, lb);
    k_mix   <<<632, 512>>>(c00, c01, c10, c11);
    k_abd_ce<<<160, 512>>>();
    k_main  <<<148, 256, SM_MAIN>>>(out);
}

// round 7
// speedup vs baseline: 2.4593x; 1.2826x over previous
#include <cuda_runtime.h>
#include <cuda_bf16.h>
#include <math.h>
#include <stdint.h>

namespace {

constexpr int B_ = 32;
constexpr int N_ = 64;
constexpr int C_ = 128;
constexpr int M_ = 15;
constexpr int E_ = B_ * N_ * N_;   // 131072
constexpr float LN_EPS = 1e-5f;
constexpr int TSTR = 136;          // padded bf16 row stride (272B: conflict-free ldmatrix)
constexpr int WSEG = 128 * TSTR;   // elements per weight segment

// ---------------- device scratch --------------------------------------------
// post-LN activations, split bf16: v = hi + lo  (32 MB each)
__device__ __align__(16) __nv_bfloat16 g_t1h[(size_t)E_ * C_];
__device__ __align__(16) __nv_bfloat16 g_t1l[(size_t)E_ * C_];
__device__ __align__(16) float g_row [B_ * N_ * C_];
__device__ __align__(16) float g_col [B_ * N_ * C_];
__device__ __align__(16) float g_diag[B_ * N_ * C_];
__device__ __align__(16) float g_A [B_ * N_ * C_];
__device__ __align__(16) float g_Bv[B_ * N_ * C_];
__device__ __align__(16) float g_D [B_ * N_ * C_];
__device__ __align__(16) float g_Cc[B_ * C_];
__device__ __align__(16) float g_Ec[B_ * C_];
__device__ __align__(16) float g_WT[M_ * C_ * C_];          // [m][c][o] (small projections)
// maps 0,1 split bf16, padded [o][k] stride 136: segs {W0hi, W0lo, W1hi, W1lo}
__device__ __align__(16) __nv_bfloat16 g_Wb[4 * WSEG];

// ---------------- helpers ----------------------------------------------------
__device__ __forceinline__ float gelu_exact(float v) {
    return 0.5f * v * (1.0f + erff(v * 0.70710678118654752440f));
}
__device__ __forceinline__ uint32_t smem_to_u32(const void* p) {
    uint32_t a;
    asm("{ .reg .u64 t; cvta.to.shared.u64 t, %1; cvt.u32.u64 %0, t; }" : "=r"(a) : "l"(p));
    return a;
}
__device__ __forceinline__ void ldsm4(uint32_t* r, uint32_t addr) {
    asm volatile("ldmatrix.sync.aligned.m8n8.x4.shared.b16 {%0,%1,%2,%3}, [%4];"
                 : "=r"(r[0]), "=r"(r[1]), "=r"(r[2]), "=r"(r[3]) : "r"(addr));
}
__device__ __forceinline__ void mma16816(float* d, const uint32_t* a,
                                         uint32_t b0, uint32_t b1) {
    asm volatile("mma.sync.aligned.m16n8k16.row.col.f32.bf16.bf16.f32 "
                 "{%0,%1,%2,%3}, {%4,%5,%6,%7}, {%8,%9}, {%0,%1,%2,%3};"
                 : "+f"(d[0]), "+f"(d[1]), "+f"(d[2]), "+f"(d[3])
                 : "r"(a[0]), "r"(a[1]), "r"(a[2]), "r"(a[3]), "r"(b0), "r"(b1));
}
__device__ __forceinline__ void cvt_split4(float4 v, uint2& h, uint2& l) {
    __nv_bfloat162 h0 = __floats2bfloat162_rn(v.x, v.y);
    __nv_bfloat162 h1 = __floats2bfloat162_rn(v.z, v.w);
    float r0 = v.x - __bfloat162float(h0.x);
    float r1 = v.y - __bfloat162float(h0.y);
    float r2 = v.z - __bfloat162float(h1.x);
    float r3 = v.w - __bfloat162float(h1.y);
    __nv_bfloat162 l0 = __floats2bfloat162_rn(r0, r1);
    __nv_bfloat162 l1 = __floats2bfloat162_rn(r2, r3);
    h.x = *reinterpret_cast<uint32_t*>(&h0); h.y = *reinterpret_cast<uint32_t*>(&h1);
    l.x = *reinterpret_cast<uint32_t*>(&l0); l.y = *reinterpret_cast<uint32_t*>(&l1);
}
__device__ __forceinline__ uint32_t split_pack(float a, float b, uint32_t& lo) {
    __nv_bfloat162 h = __floats2bfloat162_rn(a, b);
    float r0 = a - __bfloat162float(h.x);
    float r1 = b - __bfloat162float(h.y);
    __nv_bfloat162 l = __floats2bfloat162_rn(r0, r1);
    lo = *reinterpret_cast<uint32_t*>(&l);
    return *reinterpret_cast<uint32_t*>(&h);
}

#define CP_ASYNC16(dst, src) \
    asm volatile("cp.async.cg.shared.global [%0], [%1], 16;" :: "r"(dst), "l"(src))
#define CP_COMMIT() asm volatile("cp.async.commit_group;" ::: "memory")
#define CP_WAIT0()  asm volatile("cp.async.wait_group 0;" ::: "memory")

// ---------------- K1: warp-MMA input GEMM + GELU + LN + row means -----------
// Per (b,i) tile: H[64j][128o] = X @ W_in^T, then GELU, LN over o, split-store.
// smem layout (bytes):
constexpr int KI_WH = 0;               // Wi hi  [128][136] bf16 = 34816
constexpr int KI_WL = 34816;
constexpr int KI_XH = 69632;           // X hi [64][136] bf16 = 17408
constexpr int KI_XL = 87040;
constexpr int KI_BI = 104448;          // bias 128 f32
constexpr int KI_LG = 104960;
constexpr int KI_LB = 105472;
constexpr int KI_HR = 105984;          // halfred[64][2] float2 = 1024
constexpr int KI_CS = 107008;          // colsum 128 f32
constexpr int KI_SM = 107520;

__global__ void __launch_bounds__(256) k_input(
        const float* __restrict__ x, const float* __restrict__ Wi,
        const float* __restrict__ bi, const float* __restrict__ lg,
        const float* __restrict__ lb) {
    extern __shared__ __align__(16) unsigned char smem[];
    const uint32_t sb = smem_to_u32(smem);
    const int tid = threadIdx.x, wid = tid >> 5, lane = tid & 31;
    const int j0 = (wid & 3) * 16, nh = wid >> 2;
    const int rg = lane >> 2, c2 = (lane & 3) * 2;

    // stage W_in split hi/lo (once per block)
    for (int u = 0; u < 16; u++) {
        int idx = u * 256 + tid;                 // 4096 groups of 4
        int o = idx >> 5, c4 = (idx & 31) * 4;
        float4 v = *reinterpret_cast<const float4*>(Wi + o * C_ + c4);
        uint2 h, l; cvt_split4(v, h, l);
        uint32_t so = (uint32_t)(o * TSTR + c4) * 2;
        *reinterpret_cast<uint2*>(smem + KI_WH + so) = h;
        *reinterpret_cast<uint2*>(smem + KI_WL + so) = l;
    }
    if (tid < 128) {
        reinterpret_cast<float*>(smem + KI_BI)[tid] = bi[tid];
        reinterpret_cast<float*>(smem + KI_LG)[tid] = lg[tid];
        reinterpret_cast<float*>(smem + KI_LB)[tid] = lb[tid];
    }

    const uint32_t a_off = (uint32_t)((lane & 15) * TSTR + ((lane >> 4) << 3)) * 2;
    const uint32_t b_off = (uint32_t)((((lane >> 4) << 3) + (lane & 7)) * TSTR
                                      + (((lane >> 3) & 1) << 3)) * 2;
    const float* bi_s = reinterpret_cast<const float*>(smem + KI_BI);
    const float* lg_s = reinterpret_cast<const float*>(smem + KI_LG);
    const float* lb_s = reinterpret_cast<const float*>(smem + KI_LB);
    float* cs_s = reinterpret_cast<float*>(smem + KI_CS);
    float2* hr = reinterpret_cast<float2*>(smem + KI_HR);

    for (int p = blockIdx.x; p < B_ * N_; p += gridDim.x) {
        __syncthreads();
        if (tid < 128) cs_s[tid] = 0.f;
        {   // stage X split
            const float* xs = x + (size_t)p * (N_ * C_);
            for (int u = 0; u < 8; u++) {
                int idx = u * 256 + tid;
                int r = idx >> 5, c4 = (idx & 31) * 4;
                float4 v = *reinterpret_cast<const float4*>(xs + r * C_ + c4);
                uint2 h, l; cvt_split4(v, h, l);
                uint32_t so = (uint32_t)(r * TSTR + c4) * 2;
                *reinterpret_cast<uint2*>(smem + KI_XH + so) = h;
                *reinterpret_cast<uint2*>(smem + KI_XL + so) = l;
            }
        }
        __syncthreads();

        float acc[8][4];
#pragma unroll
        for (int nt = 0; nt < 8; nt++)
#pragma unroll
            for (int q = 0; q < 4; q++) acc[nt][q] = 0.f;

#pragma unroll 1
        for (int kt = 0; kt < 8; kt++) {
            const uint32_t kb = kt * 32;
            const uint32_t arow = (uint32_t)(j0 * TSTR) * 2 + a_off + kb;
            uint32_t xh[4], xl[4];
            ldsm4(xh, sb + KI_XH + arow);
            ldsm4(xl, sb + KI_XL + arow);
#pragma unroll
            for (int np = 0; np < 4; np++) {
                const uint32_t brow =
                    (uint32_t)((nh * 64 + np * 16) * TSTR) * 2 + b_off + kb;
                uint32_t wh[4], wl[4];
                ldsm4(wh, sb + KI_WH + brow);
                ldsm4(wl, sb + KI_WL + brow);
#pragma unroll
                for (int e = 0; e < 2; e++) {
                    float* d = acc[np * 2 + e];
                    const int rgi = e * 2;
                    mma16816(d, xh, wh[rgi], wh[rgi + 1]);
                    mma16816(d, xh, wl[rgi], wl[rgi + 1]);
                    mma16816(d, xl, wh[rgi], wh[rgi + 1]);
                }
            }
        }

        // ---- epilogue: bias + GELU, LN stats ----
        float sa = 0.f, ssa = 0.f, sbm = 0.f, ssb = 0.f;
#pragma unroll
        for (int nt = 0; nt < 8; nt++) {
            const int o = nh * 64 + nt * 8 + c2;
            const float b0 = bi_s[o], b1 = bi_s[o + 1];
            acc[nt][0] = gelu_exact(acc[nt][0] + b0);
            acc[nt][1] = gelu_exact(acc[nt][1] + b1);
            acc[nt][2] = gelu_exact(acc[nt][2] + b0);
            acc[nt][3] = gelu_exact(acc[nt][3] + b1);
            sa  += acc[nt][0] + acc[nt][1];
            ssa += acc[nt][0] * acc[nt][0] + acc[nt][1] * acc[nt][1];
            sbm += acc[nt][2] + acc[nt][3];
            ssb += acc[nt][2] * acc[nt][2] + acc[nt][3] * acc[nt][3];
        }
#pragma unroll
        for (int off = 1; off <= 2; off <<= 1) {
            sa  += __shfl_xor_sync(0xffffffffu, sa,  off);
            ssa += __shfl_xor_sync(0xffffffffu, ssa, off);
            sbm += __shfl_xor_sync(0xffffffffu, sbm, off);
            ssb += __shfl_xor_sync(0xffffffffu, ssb, off);
        }
        if ((lane & 3) == 0) {
            hr[(j0 + rg) * 2 + nh]     = make_float2(sa, ssa);
            hr[(j0 + rg + 8) * 2 + nh] = make_float2(sbm, ssb);
        }
        __syncthreads();
        const int ja = j0 + rg, jb = j0 + rg + 8;
        float2 ha0 = hr[ja * 2 + 0], ha1 = hr[ja * 2 + 1];
        float2 hb0 = hr[jb * 2 + 0], hb1 = hr[jb * 2 + 1];
        const float mua = (ha0.x + ha1.x) * (1.0f / C_);
        const float inva = rsqrtf((ha0.y + ha1.y) * (1.0f / C_) - mua * mua + LN_EPS);
        const float mub = (hb0.x + hb1.x) * (1.0f / C_);
        const float invb = rsqrtf((hb0.y + hb1.y) * (1.0f / C_) - mub * mub + LN_EPS);

        uint32_t* th32 = reinterpret_cast<uint32_t*>(g_t1h);
        uint32_t* tl32 = reinterpret_cast<uint32_t*>(g_t1l);
        const size_t rba = ((size_t)p * N_ + ja) * (C_ / 2);
        const size_t rbb = ((size_t)p * N_ + jb) * (C_ / 2);
#pragma unroll
        for (int nt = 0; nt < 8; nt++) {
            const int o = nh * 64 + nt * 8 + c2;
            const float g0 = lg_s[o], g1 = lg_s[o + 1];
            const float z0 = lb_s[o], z1 = lb_s[o + 1];
            float n0 = (acc[nt][0] - mua) * inva * g0 + z0;
            float n1 = (acc[nt][1] - mua) * inva * g1 + z1;
            float n2 = (acc[nt][2] - mub) * invb * g0 + z0;
            float n3 = (acc[nt][3] - mub) * invb * g1 + z1;
            uint32_t lo;
            uint32_t hi = split_pack(n0, n1, lo);
            th32[rba + (o >> 1)] = hi; tl32[rba + (o >> 1)] = lo;
            hi = split_pack(n2, n3, lo);
            th32[rbb + (o >> 1)] = hi; tl32[rbb + (o >> 1)] = lo;
            // column sums (over j) for g_row
            float cs0 = n0 + n2, cs1 = n1 + n3;
#pragma unroll
            for (int off = 4; off <= 16; off <<= 1) {
                cs0 += __shfl_xor_sync(0xffffffffu, cs0, off);
                cs1 += __shfl_xor_sync(0xffffffffu, cs1, off);
            }
            if (rg == 0) {
                atomicAdd(&cs_s[o], cs0);
                atomicAdd(&cs_s[o + 1], cs1);
            }
        }
        __syncthreads();
        if (tid < 128) g_row[p * C_ + tid] = cs_s[tid] * (1.0f / N_);
    }
}

// ---------------- K2: coeffs (+ split bf16 W0/W1) + col means + diag --------
__global__ void __launch_bounds__(512) k_mix(
        const float* __restrict__ c00, const float* __restrict__ c01,
        const float* __restrict__ c10, const float* __restrict__ c11) {
    const int bx = blockIdx.x, tid = threadIdx.x;
    if (bx < 120) {
#pragma unroll
        for (int u = 0; u < 4; u++) {
            int idx = bx * 2048 + u * 512 + tid;
            int o = idx & 127, c = (idx >> 7) & 127, m = idx >> 14;
            float v = c00[o * M_ + m] * c10[o * C_ + c] + c01[c * M_ + m] * c11[o * C_ + c];
            g_WT[idx] = v;
            if (m < 2) {
                __nv_bfloat16 hb = __float2bfloat16_rn(v);
                float rr = v - __bfloat162float(hb);
                __nv_bfloat16 lo = __float2bfloat16_rn(rr);
                g_Wb[(m * 2 + 0) * WSEG + o * TSTR + c] = hb;
                g_Wb[(m * 2 + 1) * WSEG + o * TSTR + c] = lo;
            }
        }
    } else {
        int p = (bx - 120) * 8 + (tid >> 6);
        int co = (tid & 63) * 2;
        int b = p >> 6, q = p & 63;
        const uint32_t* th32 = reinterpret_cast<const uint32_t*>(g_t1h);
        const uint32_t* tl32 = reinterpret_cast<const uint32_t*>(g_t1l);
        float s0 = 0.f, s1 = 0.f;
#pragma unroll 4
        for (int i2 = 0; i2 < N_; i2++) {
            size_t idx = ((size_t)((b * N_ + i2) * N_ + q) * C_ + co) >> 1;
            uint32_t hv = th32[idx], lv = tl32[idx];
            __nv_bfloat162 hb = *reinterpret_cast<__nv_bfloat162*>(&hv);
            __nv_bfloat162 lb2 = *reinterpret_cast<__nv_bfloat162*>(&lv);
            s0 += __bfloat162float(hb.x) + __bfloat162float(lb2.x);
            s1 += __bfloat162float(hb.y) + __bfloat162float(lb2.y);
        }
        g_col[p * C_ + co]     = s0 * (1.0f / N_);
        g_col[p * C_ + co + 1] = s1 * (1.0f / N_);
        size_t di = ((size_t)((b * N_ + q) * N_ + q) * C_ + co) >> 1;
        uint32_t hv = th32[di], lv = tl32[di];
        __nv_bfloat162 hb = *reinterpret_cast<__nv_bfloat162*>(&hv);
        __nv_bfloat162 lb2 = *reinterpret_cast<__nv_bfloat162*>(&lv);
        g_diag[p * C_ + co]     = __bfloat162float(hb.x) + __bfloat162float(lb2.x);
        g_diag[p * C_ + co + 1] = __bfloat162float(hb.y) + __bfloat162float(lb2.y);
    }
}

// ---------------- K3: A,Bv,D + Cc,Ec ----------------------------------------
__global__ void __launch_bounds__(512) k_abd_ce() {
    const int tid = threadIdx.x;
    if (blockIdx.x < 128) {
        __shared__ float s_in[3 * 16 * C_];
        float* sd = s_in;
        float* sr = s_in + 16 * C_;
        float* sc = s_in + 32 * C_;
        const int rb = blockIdx.x * 16;
        for (int idx = tid; idx < 16 * C_; idx += 512) {
            sd[idx] = g_diag[rb * C_ + idx];
            sr[idx] = g_row [rb * C_ + idx];
            sc[idx] = g_col [rb * C_ + idx];
        }
        __syncthreads();
        const int o = tid & 127, grp = tid >> 7;
        const float* W[9] = {
            g_WT + 2 * C_ * C_, g_WT + 4 * C_ * C_, g_WT + 6 * C_ * C_,
            g_WT + 3 * C_ * C_, g_WT + 5 * C_ * C_, g_WT + 7 * C_ * C_,
            g_WT + 10 * C_ * C_, g_WT + 11 * C_ * C_, g_WT + 12 * C_ * C_
        };
        float acc[4][3];
#pragma unroll
        for (int r = 0; r < 4; r++) { acc[r][0] = acc[r][1] = acc[r][2] = 0.f; }
#pragma unroll 1
        for (int c0 = 0; c0 < C_; c0 += 4) {
            float w[4][9];
#pragma unroll
            for (int u = 0; u < 4; u++) {
                int wi = (c0 + u) * C_ + o;
#pragma unroll
                for (int m = 0; m < 9; m++) w[u][m] = W[m][wi];
            }
#pragma unroll
            for (int u = 0; u < 4; u++) {
                int c = c0 + u;
#pragma unroll
                for (int r = 0; r < 4; r++) {
                    int rr = grp * 4 + r;
                    float d = sd[rr * C_ + c], ro = sr[rr * C_ + c], co = sc[rr * C_ + c];
                    acc[r][0] = fmaf(w[u][0], d, fmaf(w[u][1], ro, fmaf(w[u][2], co, acc[r][0])));
                    acc[r][1] = fmaf(w[u][3], d, fmaf(w[u][4], ro, fmaf(w[u][5], co, acc[r][1])));
                    acc[r][2] = fmaf(w[u][6], d, fmaf(w[u][7], ro, fmaf(w[u][8], co, acc[r][2])));
                }
            }
        }
#pragma unroll
        for (int r = 0; r < 4; r++) {
            int rr = rb + grp * 4 + r;
            g_A [rr * C_ + o] = acc[r][0];
            g_Bv[rr * C_ + o] = acc[r][1];
            g_D [rr * C_ + o] = acc[r][2];
        }
    } else {
        __shared__ float str[C_], sto[C_], red[8][C_];
        const int b = blockIdx.x - 128;
        if (tid < C_) {
            float st = 0.f, so = 0.f;
#pragma unroll 4
            for (int q = 0; q < N_; q++) {
                st += g_diag[(b * N_ + q) * C_ + tid];
                so += g_row [(b * N_ + q) * C_ + tid];
            }
            str[tid] = st * (1.0f / N_);
            sto[tid] = so * (1.0f / N_);
        }
        __syncthreads();
        const int o = tid & 127, grp = tid >> 7;
        const float* W8  = g_WT + 8  * C_ * C_;
        const float* W9  = g_WT + 9  * C_ * C_;
        const float* W13 = g_WT + 13 * C_ * C_;
        const float* W14 = g_WT + 14 * C_ * C_;
        float a = 0.f, e = 0.f;
        for (int c = grp * 32; c < grp * 32 + 32; c++) {
            int wi = c * C_ + o;
            float tr = str[c], to = sto[c];
            a = fmaf(W8 [wi], tr, fmaf(W9 [wi], to, a));
            e = fmaf(W13[wi], tr, fmaf(W14[wi], to, e));
        }
        red[grp][o] = a; red[4 + grp][o] = e;
        __syncthreads();
        if (tid < C_) {
            g_Cc[b * C_ + tid] = red[0][tid] + red[1][tid] + red[2][tid] + red[3][tid];
            g_Ec[b * C_ + tid] = red[4][tid] + red[5][tid] + red[6][tid] + red[7][tid];
        }
    }
}

// ---------------- K4: warp-MMA main GEMM pair + broadcasts + GELU -----------
// Staging is pure cp.async from prestored split-bf16; prefetch overlaps epilogue.
constexpr int SMB_W0H = 0;
constexpr int SMB_W0L = 34816;
constexpr int SMB_W1H = 69632;
constexpr int SMB_W1L = 104448;
constexpr int SMB_T1H = 139264;
constexpr int SMB_T1L = 156672;
constexpr int SMB_T2H = 174080;
constexpr int SMB_T2L = 191488;
constexpr int SM_MAIN = 208896;

__global__ void __launch_bounds__(256) k_main(float* __restrict__ out) {
    extern __shared__ __align__(16) unsigned char smem[];
    const uint32_t sb = smem_to_u32(smem);
    const int tid = threadIdx.x, wid = tid >> 5, lane = tid & 31;
    const int j0 = (wid & 3) * 16;
    const int nh = wid >> 2;

    {   // resident weights (prepacked split layout)
        const uint4* src = reinterpret_cast<const uint4*>(g_Wb);
        uint4* dst = reinterpret_cast<uint4*>(smem);
        for (int i = tid; i < 4 * WSEG * 2 / 16; i += 256) dst[i] = src[i];
    }

    const uint32_t a_off = (uint32_t)((lane & 15) * TSTR + ((lane >> 4) << 3)) * 2;
    const uint32_t b_off = (uint32_t)((((lane >> 4) << 3) + (lane & 7)) * TSTR
                                      + (((lane >> 3) & 1) << 3)) * 2;

    auto stage = [&](int p) {   // 16 cp.async x 16B per thread
        const int b = p >> 6, i = p & 63;
        const char* s1h = reinterpret_cast<const char*>(g_t1h + (size_t)p * (N_ * C_));
        const char* s1l = reinterpret_cast<const char*>(g_t1l + (size_t)p * (N_ * C_));
#pragma unroll
        for (int u = 0; u < 4; u++) {
            int ch = u * 256 + tid;         // 0..1023
            int r = ch >> 4, c = ch & 15;
            uint32_t dso = (uint32_t)(r * TSTR + c * 8) * 2;
            CP_ASYNC16(sb + SMB_T1H + dso, s1h + ch * 16);
            CP_ASYNC16(sb + SMB_T1L + dso, s1l + ch * 16);
            const size_t r2 = ((size_t)((b * N_ + r) * N_ + i)) * C_;
            CP_ASYNC16(sb + SMB_T2H + dso, reinterpret_cast<const char*>(g_t1h + r2) + c * 16);
            CP_ASYNC16(sb + SMB_T2L + dso, reinterpret_cast<const char*>(g_t1l + r2) + c * 16);
        }
    };

    int p = blockIdx.x;
    if (p < B_ * N_) { stage(p); CP_COMMIT(); }
    CP_WAIT0();
    __syncthreads();

    for (; p < B_ * N_; p += gridDim.x) {
        const int b = p >> 6, i = p & 63;

        // ---- MMA mainloop ----
        float acc[8][4];
#pragma unroll
        for (int nt = 0; nt < 8; nt++)
#pragma unroll
            for (int q = 0; q < 4; q++) acc[nt][q] = 0.f;

#pragma unroll 1
        for (int kt = 0; kt < 8; kt++) {
            const uint32_t kb = kt * 32;
            const uint32_t arow = (uint32_t)(j0 * TSTR) * 2 + a_off + kb;
            uint32_t a1h[4], a1l[4], a2h[4], a2l[4];
            ldsm4(a1h, sb + SMB_T1H + arow);
            ldsm4(a1l, sb + SMB_T1L + arow);
            ldsm4(a2h, sb + SMB_T2H + arow);
            ldsm4(a2l, sb + SMB_T2L + arow);
#pragma unroll
            for (int np = 0; np < 4; np++) {
                const uint32_t brow =
                    (uint32_t)((nh * 64 + np * 16) * TSTR) * 2 + b_off + kb;
                uint32_t w0h[4], w0l[4], w1h[4], w1l[4];
                ldsm4(w0h, sb + SMB_W0H + brow);
                ldsm4(w0l, sb + SMB_W0L + brow);
                ldsm4(w1h, sb + SMB_W1H + brow);
                ldsm4(w1l, sb + SMB_W1L + brow);
#pragma unroll
                for (int e = 0; e < 2; e++) {
                    float* d = acc[np * 2 + e];
                    const int rgi = e * 2;
                    mma16816(d, a1h, w0h[rgi], w0h[rgi + 1]);
                    mma16816(d, a1h, w0l[rgi], w0l[rgi + 1]);
                    mma16816(d, a1l, w0h[rgi], w0h[rgi + 1]);
                    mma16816(d, a2h, w1h[rgi], w1h[rgi + 1]);
                    mma16816(d, a2h, w1l[rgi], w1l[rgi + 1]);
                    mma16816(d, a2l, w1h[rgi], w1h[rgi + 1]);
                }
            }
        }
        __syncthreads();                      // all warps done reading T smem
        const int pn = p + gridDim.x;
        if (pn < B_ * N_) { stage(pn); CP_COMMIT(); }   // prefetch overlaps epilogue

        // ---- epilogue: broadcasts + GELU + store (register/gmem only) ----
        {
            const int rg = lane >> 2;
            const int c2 = (lane & 3) * 2;
            const int ja = j0 + rg, jb = j0 + rg + 8;
            const float* Ap  = g_A  + (size_t)p * C_;
            const float* Ccp = g_Cc + (size_t)b * C_;
            const float* Dp  = g_D  + (size_t)p * C_;
            const float* Ep  = g_Ec + (size_t)b * C_;
            const float* Bva = g_Bv + ((size_t)(b * N_ + ja)) * C_;
            const float* Bvb = g_Bv + ((size_t)(b * N_ + jb)) * C_;
            float* outa = out + ((size_t)p * N_ + ja) * C_;
            float* outb = out + ((size_t)p * N_ + jb) * C_;
            const bool da = (ja == i), db = (jb == i);
#pragma unroll
            for (int nt = 0; nt < 8; nt++) {
                const int o = nh * 64 + nt * 8 + c2;
                float2 av = *reinterpret_cast<const float2*>(Ap + o);
                float2 cv = *reinterpret_cast<const float2*>(Ccp + o);
                const float addx = av.x + cv.x, addy = av.y + cv.y;
                float2 dd, ee;
                if (da || db) {
                    dd = *reinterpret_cast<const float2*>(Dp + o);
                    ee = *reinterpret_cast<const float2*>(Ep + o);
                }
                {
                    float2 bv = *reinterpret_cast<const float2*>(Bva + o);
                    float e0 = acc[nt][0] + addx + bv.x;
                    float e1 = acc[nt][1] + addy + bv.y;
                    if (da) { e0 += dd.x + ee.x; e1 += dd.y + ee.y; }
                    float2 o2; o2.x = gelu_exact(e0); o2.y = gelu_exact(e1);
                    *reinterpret_cast<float2*>(outa + o) = o2;
                }
                {
                    float2 bv = *reinterpret_cast<const float2*>(Bvb + o);
                    float e0 = acc[nt][2] + addx + bv.x;
                    float e1 = acc[nt][3] + addy + bv.y;
                    if (db) { e0 += dd.x + ee.x; e1 += dd.y + ee.y; }
                    float2 o2; o2.x = gelu_exact(e0); o2.y = gelu_exact(e1);
                    *reinterpret_cast<float2*>(outb + o) = o2;
                }
            }
        }
        CP_WAIT0();
        __syncthreads();
    }
}

} // anonymous namespace

// ---------------- launch -----------------------------------------------------
extern "C" void kernel_launch(void* const* d_in, const int* in_sizes, int n_in,
                              void* d_out, int out_size) {
    const float* x   = (const float*)d_in[0];
    const float* Wi  = (const float*)d_in[3];
    const float* bi  = (const float*)d_in[4];
    const float* lg  = (const float*)d_in[5];
    const float* lb  = (const float*)d_in[6];
    const float* c00 = (const float*)d_in[7];
    const float* c01 = (const float*)d_in[8];
    const float* c10 = (const float*)d_in[9];
    const float* c11 = (const float*)d_in[10];
    float* out = (float*)d_out;

    cudaFuncSetAttribute(k_input, cudaFuncAttributeMaxDynamicSharedMemorySize, KI_SM);
    cudaFuncSetAttribute(k_main,  cudaFuncAttributeMaxDynamicSharedMemorySize, SM_MAIN);

    k_input <<<296, 256, KI_SM>>>(x, Wi, bi, lg, lb);   // 2 blocks/SM, warp-MMA
    k_mix   <<<376, 512>>>(c00, c01, c10, c11);         // coeffs + col/diag (bf16)
    k_abd_ce<<<160, 512>>>();                           // A,Bv,D + Cc,Ec
    k_main  <<<148, 256, SM_MAIN>>>(out);               // persistent, cp.async overlap
}